// round 3
// baseline (speedup 1.0000x reference)
#include <cuda_runtime.h>
#include <cuda_fp16.h>
#include <stdint.h>

#define DIM 4096
#define NHEADS 32
#define HD 128
#define BSZ 4
#define SEQ 512
#define MAXSEQ 2048

// ---------------- scratch (device globals; no allocation in kernel_launch) ----------------
static __device__ __align__(256) float  g_q[(size_t)BSZ * SEQ * DIM];
static __device__ __align__(256) float  g_k[(size_t)BSZ * SEQ * DIM];
static __device__ __align__(256) float  g_v[(size_t)BSZ * SEQ * DIM];
static __device__ __align__(256) float  g_sc[(size_t)BSZ * NHEADS * SEQ * SEQ];
static __device__ __align__(256) __half g_xh[(size_t)BSZ * SEQ * DIM];
static __device__ __align__(256) __half g_attnh[(size_t)BSZ * SEQ * DIM];
static __device__ __align__(256) __half g_wh[(size_t)4 * DIM * DIM];

// ---------------- helpers ----------------
__device__ __forceinline__ uint32_t smem_u32(const void* p) {
    uint32_t r;
    asm("{ .reg .u64 t; cvta.to.shared.u64 t, %1; cvt.u32.u64 %0, t; }" : "=r"(r) : "l"(p));
    return r;
}

__device__ __forceinline__ void cp16(uint32_t d, const void* g) {
    asm volatile("cp.async.cg.shared.global [%0], [%1], 16;" :: "r"(d), "l"(g) : "memory");
}
#define CP_COMMIT() asm volatile("cp.async.commit_group;" ::: "memory")
#define CP_WAIT1()  asm volatile("cp.async.wait_group 1;" ::: "memory")

__device__ __forceinline__ void mma_16816(float* c, const uint32_t* a, const uint32_t* b) {
    asm volatile(
        "mma.sync.aligned.m16n8k16.row.col.f32.f16.f16.f32 "
        "{%0,%1,%2,%3}, {%4,%5,%6,%7}, {%8,%9}, {%0,%1,%2,%3};\n"
        : "+f"(c[0]), "+f"(c[1]), "+f"(c[2]), "+f"(c[3])
        : "r"(a[0]), "r"(a[1]), "r"(a[2]), "r"(a[3]),
          "r"(b[0]), "r"(b[1]));
}

__device__ __forceinline__ uint32_t pack_halves(__half lo, __half hi) {
    __half2 t = __halves2half2(lo, hi);
    return *reinterpret_cast<uint32_t*>(&t);
}

constexpr int BM = 128, BN = 128, BK = 32, PADH = 8;
constexpr float NEGBIG = -1e30f;
constexpr float QK_SCALE = 0.08838834764831845f;  // 1/sqrt(128)

// =====================================================================
//   gemm_h: C[m][n] = scale[n] * sum_k A[m][k] * B[n][k]
//   A fp16 [M,4096], B fp16 [4096,4096] (both K-major), C fp32 [M,4096]
//   128x128 tile, BK=64, 3-stage cp.async pipeline, 256 threads.
// =====================================================================
constexpr int H_BK = 64;
constexpr int HP = 72;                    // smem pitch in halves (144B, 16B-aligned)
constexpr int H_STAGE = 128 * HP;         // halves per stage per matrix
constexpr int H_SMEM_BYTES = 2 * 3 * H_STAGE * 2;  // 110592

__global__ __launch_bounds__(256) void gemm_h(
    const __half* __restrict__ A, const __half* __restrict__ B,
    const float* __restrict__ scale, float* __restrict__ C)
{
    extern __shared__ __half sm[];
    __half* As = sm;                      // [3][128][72]
    __half* Bs = sm + 3 * H_STAGE;

    const int K = DIM;
    const int tid  = threadIdx.x;
    const int warp = tid >> 5, lane = tid & 31;
    const int m0 = blockIdx.y * 128, n0 = blockIdx.x * 128;
    const int gid = lane >> 2, t2 = (lane & 3) * 2;
    const int wm = (warp & 1) * 64, wn = (warp >> 1) * 32;
    const int lrow = tid >> 1, lcol = (tid & 1) * 32;   // loader: 2 threads/row, 64B each

    const __half* Ag = A + (size_t)(m0 + lrow) * K + lcol;
    const __half* Bg = B + (size_t)(n0 + lrow) * K + lcol;

    uint32_t aBase[3], bBase[3];
#pragma unroll
    for (int s = 0; s < 3; s++) {
        aBase[s] = smem_u32(As + ((size_t)s * 128 + lrow) * HP + lcol);
        bBase[s] = smem_u32(Bs + ((size_t)s * 128 + lrow) * HP + lcol);
    }

    float c[4][4][4];
#pragma unroll
    for (int mt = 0; mt < 4; mt++)
#pragma unroll
        for (int nt = 0; nt < 4; nt++)
#pragma unroll
            for (int r = 0; r < 4; r++) c[mt][nt][r] = 0.f;

    // prologue: stages 0,1
#pragma unroll
    for (int s = 0; s < 2; s++) {
        const __half* ag = Ag + s * H_BK;
        const __half* bg = Bg + s * H_BK;
#pragma unroll
        for (int ch = 0; ch < 4; ch++) {
            cp16(aBase[s] + ch * 16, ag + ch * 8);
            cp16(bBase[s] + ch * 16, bg + ch * 8);
        }
        CP_COMMIT();
    }

    const int NK = K / H_BK;  // 64
    int s = 0;
    for (int kt = 0; kt < NK; kt++) {
        CP_WAIT1();
        __syncthreads();

        // prefetch stage kt+2 into the buffer freed by iteration kt-1
        if (kt + 2 < NK) {
            int sn = s + 2; if (sn >= 3) sn -= 3;
            const __half* ag = Ag + (kt + 2) * H_BK;
            const __half* bg = Bg + (kt + 2) * H_BK;
#pragma unroll
            for (int ch = 0; ch < 4; ch++) {
                cp16(aBase[sn] + ch * 16, ag + ch * 8);
                cp16(bBase[sn] + ch * 16, bg + ch * 8);
            }
        }
        CP_COMMIT();

        const __half* Asb = As + (size_t)s * H_STAGE;
        const __half* Bsb = Bs + (size_t)s * H_STAGE;
#pragma unroll
        for (int kk = 0; kk < H_BK; kk += 16) {
            uint32_t af[4][4], bf[4][2];
#pragma unroll
            for (int mt = 0; mt < 4; mt++) {
                const __half* p0 = Asb + (size_t)(wm + mt * 16 + gid) * HP + kk + t2;
                af[mt][0] = *(const uint32_t*)p0;
                af[mt][1] = *(const uint32_t*)(p0 + 8 * HP);
                af[mt][2] = *(const uint32_t*)(p0 + 8);
                af[mt][3] = *(const uint32_t*)(p0 + 8 * HP + 8);
            }
#pragma unroll
            for (int nt = 0; nt < 4; nt++) {
                const __half* q0 = Bsb + (size_t)(wn + nt * 8 + gid) * HP + kk + t2;
                bf[nt][0] = *(const uint32_t*)q0;
                bf[nt][1] = *(const uint32_t*)(q0 + 8);
            }
#pragma unroll
            for (int mt = 0; mt < 4; mt++)
#pragma unroll
                for (int nt = 0; nt < 4; nt++) mma_16816(c[mt][nt], af[mt], bf[nt]);
        }
        if (++s == 3) s = 0;
    }

#pragma unroll
    for (int nt = 0; nt < 4; nt++) {
        const int col = n0 + wn + nt * 8 + t2;
        const float s0 = scale[col], s1 = scale[col + 1];
#pragma unroll
        for (int mt = 0; mt < 4; mt++) {
            const int row = m0 + wm + mt * 16 + gid;
            C[(size_t)row * DIM + col]           = c[mt][nt][0] * s0;
            C[(size_t)row * DIM + col + 1]       = c[mt][nt][1] * s1;
            C[(size_t)(row + 8) * DIM + col]     = c[mt][nt][2] * s0;
            C[(size_t)(row + 8) * DIM + col + 1] = c[mt][nt][3] * s1;
        }
    }
}

// =====================================================================
// conversion kernels
// =====================================================================
__global__ void conv_w_kernel(const int4* __restrict__ w, __half* __restrict__ out, int n4)
{
    for (int i = blockIdx.x * blockDim.x + threadIdx.x; i < n4; i += gridDim.x * blockDim.x) {
        const int4 v = w[i];
        __half2 h0 = __halves2half2(__int2half_rn(v.x), __int2half_rn(v.y));
        __half2 h1 = __halves2half2(__int2half_rn(v.z), __int2half_rn(v.w));
        uint2 u;
        u.x = *reinterpret_cast<uint32_t*>(&h0);
        u.y = *reinterpret_cast<uint32_t*>(&h1);
        ((uint2*)out)[i] = u;
    }
}

__global__ void conv_x_kernel(const float4* __restrict__ x, __half* __restrict__ out, int n4)
{
    for (int i = blockIdx.x * blockDim.x + threadIdx.x; i < n4; i += gridDim.x * blockDim.x) {
        const float4 v = x[i];
        __half2 h0 = __floats2half2_rn(v.x, v.y);
        __half2 h1 = __floats2half2_rn(v.z, v.w);
        uint2 u;
        u.x = *reinterpret_cast<uint32_t*>(&h0);
        u.y = *reinterpret_cast<uint32_t*>(&h1);
        ((uint2*)out)[i] = u;
    }
}

// =====================================================================
// RoPE on q,k (in place) + scatter k,v into cache output.
// =====================================================================
__global__ void rope_cache_kernel(const float* __restrict__ fcos, const float* __restrict__ fsin,
                                  const int* __restrict__ idx,
                                  float* __restrict__ cacheK, float* __restrict__ cacheV)
{
    const int bs = blockIdx.x;
    const int h  = blockIdx.y;
    const int i  = threadIdx.x;
    const int b  = bs >> 9, s = bs & 511;
    const size_t base = (size_t)bs * DIM + (size_t)h * HD;

    const float cv = fcos[s * 64 + i];
    const float sv = fsin[s * 64 + i];

    const float qr = g_q[base + 2 * i], qi = g_q[base + 2 * i + 1];
    g_q[base + 2 * i]     = qr * cv - qi * sv;
    g_q[base + 2 * i + 1] = qr * sv + qi * cv;

    const float kr = g_k[base + 2 * i], ki = g_k[base + 2 * i + 1];
    const float kor = kr * cv - ki * sv;
    const float koi = kr * sv + ki * cv;
    g_k[base + 2 * i]     = kor;
    g_k[base + 2 * i + 1] = koi;

    const int t = idx[s];
    const size_t cb = ((size_t)(b * MAXSEQ + t) * NHEADS + h) * HD;
    cacheK[cb + 2 * i]     = kor;
    cacheK[cb + 2 * i + 1] = koi;
    cacheV[cb + 2 * i]     = g_v[base + 2 * i];
    cacheV[cb + 2 * i + 1] = g_v[base + 2 * i + 1];
}

__global__ void zero_tail_kernel(float4* __restrict__ ck, float4* __restrict__ cv)
{
    const int perB = 1536 * 1024;
    const int n = BSZ * perB;
    const float4 z = make_float4(0.f, 0.f, 0.f, 0.f);
    for (int i = blockIdx.x * blockDim.x + threadIdx.x; i < n; i += gridDim.x * blockDim.x) {
        const int b = i / perB, r = i - b * perB;
        const size_t off = ((size_t)b * MAXSEQ + SEQ) * (DIM / 4) + r;
        ck[off] = z;
        cv[off] = z;
    }
}

// =====================================================================
// QK^T scores with causal mask
// =====================================================================
__global__ __launch_bounds__(256) void gemm_qk_kernel()
{
    const int z = blockIdx.z;
    const int b = z >> 5, h = z & 31;
    const int m0 = blockIdx.y * BM, n0 = blockIdx.x * BN;
    float* Cp = g_sc + (size_t)z * SEQ * SEQ;

    if (n0 >= m0 + BM) {
        for (int i = threadIdx.x; i < BM * BN; i += 256)
            Cp[(size_t)(m0 + i / BN) * SEQ + n0 + (i % BN)] = NEGBIG;
        return;
    }

    const float* Aq = g_q + (size_t)b * SEQ * DIM + (size_t)h * HD;
    const float* Bk = g_k + (size_t)b * SEQ * DIM + (size_t)h * HD;

    __shared__ __half As[2][BM][BK + PADH];
    __shared__ __half Bs[2][BN][BK + PADH];

    const int tid  = threadIdx.x;
    const int warp = tid >> 5, lane = tid & 31;
    const int gid  = lane >> 2, t2 = (lane & 3) * 2;
    const int wm   = (warp & 1) * 64, wn = (warp >> 1) * 32;
    const int lrow = tid >> 3, lcol = (tid & 7) * 4;

    float c[4][4][4];
#pragma unroll
    for (int mt = 0; mt < 4; mt++)
#pragma unroll
        for (int nt = 0; nt < 4; nt++)
#pragma unroll
            for (int r = 0; r < 4; r++) c[mt][nt][r] = 0.f;

    float4 aN[4], bN[4];
#pragma unroll
    for (int i = 0; i < 4; i++) {
        aN[i] = *(const float4*)(Aq + (size_t)(m0 + lrow + 32 * i) * DIM + lcol);
        bN[i] = *(const float4*)(Bk + (size_t)(n0 + lrow + 32 * i) * DIM + lcol);
    }
#pragma unroll
    for (int i = 0; i < 4; i++) {
        __half2* pa = (__half2*)&As[0][lrow + 32 * i][lcol];
        pa[0] = __floats2half2_rn(aN[i].x, aN[i].y);
        pa[1] = __floats2half2_rn(aN[i].z, aN[i].w);
        __half2* pb = (__half2*)&Bs[0][lrow + 32 * i][lcol];
        pb[0] = __floats2half2_rn(bN[i].x, bN[i].y);
        pb[1] = __floats2half2_rn(bN[i].z, bN[i].w);
    }
    __syncthreads();

    const int nk = HD / BK;  // 4
    for (int kt = 0; kt < nk; kt++) {
        const int buf = kt & 1;
        const bool has_next = (kt + 1 < nk);
        if (has_next) {
#pragma unroll
            for (int i = 0; i < 4; i++) {
                aN[i] = *(const float4*)(Aq + (size_t)(m0 + lrow + 32 * i) * DIM + (kt + 1) * BK + lcol);
                bN[i] = *(const float4*)(Bk + (size_t)(n0 + lrow + 32 * i) * DIM + (kt + 1) * BK + lcol);
            }
        }
#pragma unroll
        for (int kk = 0; kk < BK; kk += 16) {
            uint32_t af[4][4], bf[4][2];
#pragma unroll
            for (int mt = 0; mt < 4; mt++) {
                const int r = wm + mt * 16 + gid;
                af[mt][0] = *(const uint32_t*)&As[buf][r][kk + t2];
                af[mt][1] = *(const uint32_t*)&As[buf][r + 8][kk + t2];
                af[mt][2] = *(const uint32_t*)&As[buf][r][kk + t2 + 8];
                af[mt][3] = *(const uint32_t*)&As[buf][r + 8][kk + t2 + 8];
            }
#pragma unroll
            for (int nt = 0; nt < 4; nt++) {
                const int rn = wn + nt * 8 + gid;
                bf[nt][0] = *(const uint32_t*)&Bs[buf][rn][kk + t2];
                bf[nt][1] = *(const uint32_t*)&Bs[buf][rn][kk + t2 + 8];
            }
#pragma unroll
            for (int mt = 0; mt < 4; mt++)
#pragma unroll
                for (int nt = 0; nt < 4; nt++) mma_16816(c[mt][nt], af[mt], bf[nt]);
        }
        if (has_next) {
#pragma unroll
            for (int i = 0; i < 4; i++) {
                __half2* pa = (__half2*)&As[buf ^ 1][lrow + 32 * i][lcol];
                pa[0] = __floats2half2_rn(aN[i].x, aN[i].y);
                pa[1] = __floats2half2_rn(aN[i].z, aN[i].w);
                __half2* pb = (__half2*)&Bs[buf ^ 1][lrow + 32 * i][lcol];
                pb[0] = __floats2half2_rn(bN[i].x, bN[i].y);
                pb[1] = __floats2half2_rn(bN[i].z, bN[i].w);
            }
        }
        __syncthreads();
    }

#pragma unroll
    for (int mt = 0; mt < 4; mt++)
#pragma unroll
        for (int nt = 0; nt < 4; nt++) {
            const int row = m0 + wm + mt * 16 + gid;
            const int col = n0 + wn + nt * 8 + t2;
            float v0 = c[mt][nt][0] * QK_SCALE; if (col > row)         v0 = NEGBIG;
            float v1 = c[mt][nt][1] * QK_SCALE; if (col + 1 > row)     v1 = NEGBIG;
            float v2 = c[mt][nt][2] * QK_SCALE; if (col > row + 8)     v2 = NEGBIG;
            float v3 = c[mt][nt][3] * QK_SCALE; if (col + 1 > row + 8) v3 = NEGBIG;
            Cp[(size_t)row * SEQ + col]           = v0;
            Cp[(size_t)row * SEQ + col + 1]       = v1;
            Cp[(size_t)(row + 8) * SEQ + col]     = v2;
            Cp[(size_t)(row + 8) * SEQ + col + 1] = v3;
        }
}

// =====================================================================
// Row softmax
// =====================================================================
__global__ __launch_bounds__(256) void softmax_kernel()
{
    const int row  = blockIdx.x * 8 + (threadIdx.x >> 5);
    const int lane = threadIdx.x & 31;
    float* p = g_sc + (size_t)row * SEQ;

    float4 v[4];
    float mx = -3.4e38f;
#pragma unroll
    for (int i = 0; i < 4; i++) {
        v[i] = *(float4*)(p + lane * 4 + i * 128);
        mx = fmaxf(mx, fmaxf(fmaxf(v[i].x, v[i].y), fmaxf(v[i].z, v[i].w)));
    }
#pragma unroll
    for (int o = 16; o > 0; o >>= 1) mx = fmaxf(mx, __shfl_xor_sync(0xffffffffu, mx, o));

    float s = 0.f;
#pragma unroll
    for (int i = 0; i < 4; i++) {
        v[i].x = __expf(v[i].x - mx);
        v[i].y = __expf(v[i].y - mx);
        v[i].z = __expf(v[i].z - mx);
        v[i].w = __expf(v[i].w - mx);
        s += v[i].x + v[i].y + v[i].z + v[i].w;
    }
#pragma unroll
    for (int o = 16; o > 0; o >>= 1) s += __shfl_xor_sync(0xffffffffu, s, o);
    const float r = 1.f / s;
#pragma unroll
    for (int i = 0; i < 4; i++) {
        v[i].x *= r; v[i].y *= r; v[i].z *= r; v[i].w *= r;
        *(float4*)(p + lane * 4 + i * 128) = v[i];
    }
}

// =====================================================================
// PV: writes g_attnh (fp16) for the final gemm_h
// =====================================================================
__global__ __launch_bounds__(256) void gemm_pv_kernel()
{
    const int z = blockIdx.z;
    const int b = z >> 5, h = z & 31;
    const int m0 = blockIdx.y * BM;
    const float* Ap = g_sc + (size_t)z * SEQ * SEQ;
    const float* Vp = g_v + (size_t)b * SEQ * DIM + (size_t)h * HD;

    __shared__ __half As[2][BM][BK + PADH];
    __shared__ __half Bs[2][BK][BN + PADH];

    const int tid  = threadIdx.x;
    const int warp = tid >> 5, lane = tid & 31;
    const int gid  = lane >> 2, t2 = (lane & 3) * 2;
    const int wm   = (warp & 1) * 64, wn = (warp >> 1) * 32;
    const int lrow = tid >> 3, lcol = (tid & 7) * 4;
    const int krow = tid >> 5, kcol = (tid & 31) * 4;

    float c[4][4][4];
#pragma unroll
    for (int mt = 0; mt < 4; mt++)
#pragma unroll
        for (int nt = 0; nt < 4; nt++)
#pragma unroll
            for (int r = 0; r < 4; r++) c[mt][nt][r] = 0.f;

    float4 aN[4], bN[4];
#pragma unroll
    for (int i = 0; i < 4; i++) {
        aN[i] = *(const float4*)(Ap + (size_t)(m0 + lrow + 32 * i) * SEQ + lcol);
        bN[i] = *(const float4*)(Vp + (size_t)(krow + 8 * i) * DIM + kcol);
    }
#pragma unroll
    for (int i = 0; i < 4; i++) {
        __half2* pa = (__half2*)&As[0][lrow + 32 * i][lcol];
        pa[0] = __floats2half2_rn(aN[i].x, aN[i].y);
        pa[1] = __floats2half2_rn(aN[i].z, aN[i].w);
        __half2* pb = (__half2*)&Bs[0][krow + 8 * i][kcol];
        pb[0] = __floats2half2_rn(bN[i].x, bN[i].y);
        pb[1] = __floats2half2_rn(bN[i].z, bN[i].w);
    }
    __syncthreads();

    const int nk = SEQ / BK;  // 16
    for (int kt = 0; kt < nk; kt++) {
        const int buf = kt & 1;
        const bool has_next = (kt + 1 < nk);
        if (has_next) {
#pragma unroll
            for (int i = 0; i < 4; i++) {
                aN[i] = *(const float4*)(Ap + (size_t)(m0 + lrow + 32 * i) * SEQ + (kt + 1) * BK + lcol);
                bN[i] = *(const float4*)(Vp + (size_t)((kt + 1) * BK + krow + 8 * i) * DIM + kcol);
            }
        }
#pragma unroll
        for (int kk = 0; kk < BK; kk += 16) {
            uint32_t af[4][4], bf[4][2];
#pragma unroll
            for (int mt = 0; mt < 4; mt++) {
                const int r = wm + mt * 16 + gid;
                af[mt][0] = *(const uint32_t*)&As[buf][r][kk + t2];
                af[mt][1] = *(const uint32_t*)&As[buf][r + 8][kk + t2];
                af[mt][2] = *(const uint32_t*)&As[buf][r][kk + t2 + 8];
                af[mt][3] = *(const uint32_t*)&As[buf][r + 8][kk + t2 + 8];
            }
#pragma unroll
            for (int nt = 0; nt < 4; nt++) {
                const int nn = wn + nt * 8 + gid;
                bf[nt][0] = pack_halves(Bs[buf][kk + t2][nn],     Bs[buf][kk + t2 + 1][nn]);
                bf[nt][1] = pack_halves(Bs[buf][kk + t2 + 8][nn], Bs[buf][kk + t2 + 9][nn]);
            }
#pragma unroll
            for (int mt = 0; mt < 4; mt++)
#pragma unroll
                for (int nt = 0; nt < 4; nt++) mma_16816(c[mt][nt], af[mt], bf[nt]);
        }
        if (has_next) {
#pragma unroll
            for (int i = 0; i < 4; i++) {
                __half2* pa = (__half2*)&As[buf ^ 1][lrow + 32 * i][lcol];
                pa[0] = __floats2half2_rn(aN[i].x, aN[i].y);
                pa[1] = __floats2half2_rn(aN[i].z, aN[i].w);
                __half2* pb = (__half2*)&Bs[buf ^ 1][krow + 8 * i][kcol];
                pb[0] = __floats2half2_rn(bN[i].x, bN[i].y);
                pb[1] = __floats2half2_rn(bN[i].z, bN[i].w);
            }
        }
        __syncthreads();
    }

#pragma unroll
    for (int mt = 0; mt < 4; mt++)
#pragma unroll
        for (int nt = 0; nt < 4; nt++) {
            const int row = m0 + wm + mt * 16 + gid;
            const int col = wn + nt * 8 + t2;
            __half* d0 = g_attnh + (size_t)(b * SEQ + row) * DIM + (size_t)h * HD;
            __half* d1 = g_attnh + (size_t)(b * SEQ + row + 8) * DIM + (size_t)h * HD;
            *(__half2*)(d0 + col) = __floats2half2_rn(c[mt][nt][0], c[mt][nt][1]);
            *(__half2*)(d1 + col) = __floats2half2_rn(c[mt][nt][2], c[mt][nt][3]);
        }
}

// =====================================================================
extern "C" void kernel_launch(void* const* d_in, const int* in_sizes, int n_in,
                              void* d_out, int out_size)
{
    (void)in_sizes; (void)n_in; (void)out_size;
    const float* x    = (const float*)d_in[0];
    const float* fcos = (const float*)d_in[1];
    const float* fsin = (const float*)d_in[2];
    const int*   idx  = (const int*)d_in[4];
    const int*   wq   = (const int*)d_in[7];
    const float* sq   = (const float*)d_in[8];
    const int*   wk   = (const int*)d_in[9];
    const float* sk   = (const float*)d_in[10];
    const int*   wv   = (const int*)d_in[11];
    const float* sv   = (const float*)d_in[12];
    const int*   wo   = (const int*)d_in[13];
    const float* so   = (const float*)d_in[14];

    float* out    = (float*)d_out;
    float* cacheK = out + (size_t)BSZ * SEQ * DIM;
    float* cacheV = cacheK + (size_t)BSZ * MAXSEQ * NHEADS * HD;

    float  *pq = nullptr, *pk = nullptr, *pv = nullptr;
    __half *pxh = nullptr, *pwh = nullptr, *pah = nullptr;
    cudaGetSymbolAddress((void**)&pq, g_q);
    cudaGetSymbolAddress((void**)&pk, g_k);
    cudaGetSymbolAddress((void**)&pv, g_v);
    cudaGetSymbolAddress((void**)&pxh, g_xh);
    cudaGetSymbolAddress((void**)&pwh, g_wh);
    cudaGetSymbolAddress((void**)&pah, g_attnh);

    cudaFuncSetAttribute(gemm_h, cudaFuncAttributeMaxDynamicSharedMemorySize, H_SMEM_BYTES);

    const size_t W = (size_t)DIM * DIM;

    // 1) conversions (fp16 once)
    conv_x_kernel<<<1184, 256>>>((const float4*)x, pxh, (int)(BSZ * SEQ * DIM / 4));
    conv_w_kernel<<<2368, 256>>>((const int4*)wq, pwh + 0 * W, (int)(W / 4));
    conv_w_kernel<<<2368, 256>>>((const int4*)wk, pwh + 1 * W, (int)(W / 4));
    conv_w_kernel<<<2368, 256>>>((const int4*)wv, pwh + 2 * W, (int)(W / 4));
    conv_w_kernel<<<2368, 256>>>((const int4*)wo, pwh + 3 * W, (int)(W / 4));

    // 2) QKV projections
    dim3 gw(DIM / 128, (BSZ * SEQ) / 128);  // (32, 16)
    gemm_h<<<gw, 256, H_SMEM_BYTES>>>(pxh, pwh + 0 * W, sq, pq);
    gemm_h<<<gw, 256, H_SMEM_BYTES>>>(pxh, pwh + 1 * W, sk, pk);
    gemm_h<<<gw, 256, H_SMEM_BYTES>>>(pxh, pwh + 2 * W, sv, pv);

    // 3) RoPE + cache scatter + tail zero
    rope_cache_kernel<<<dim3(BSZ * SEQ, NHEADS), 64>>>(fcos, fsin, idx, cacheK, cacheV);
    zero_tail_kernel<<<2048, 256>>>((float4*)cacheK, (float4*)cacheV);

    // 4) attention middle
    gemm_qk_kernel<<<dim3(SEQ / BN, SEQ / BM, BSZ * NHEADS), 256>>>();
    softmax_kernel<<<(BSZ * NHEADS * SEQ) / 8, 256>>>();
    gemm_pv_kernel<<<dim3(1, SEQ / BM, BSZ * NHEADS), 256>>>();

    // 5) output projection
    gemm_h<<<gw, 256, H_SMEM_BYTES>>>(pah, pwh + 3 * W, so, out);
}

// round 4
// speedup vs baseline: 1.4071x; 1.4071x over previous
#include <cuda_runtime.h>
#include <cuda_fp16.h>
#include <stdint.h>

#define DIM 4096
#define NHEADS 32
#define HD 128
#define BSZ 4
#define SEQ 512
#define MAXSEQ 2048

// ---------------- scratch ----------------
static __device__ __align__(256) float  g_q[(size_t)BSZ * SEQ * DIM];
static __device__ __align__(256) float  g_k[(size_t)BSZ * SEQ * DIM];
static __device__ __align__(256) float  g_v[(size_t)BSZ * SEQ * DIM];
static __device__ __align__(256) float  g_sc[(size_t)BSZ * NHEADS * SEQ * SEQ];
static __device__ __align__(256) __half g_xh[(size_t)BSZ * SEQ * DIM];
static __device__ __align__(256) __half g_attnh[(size_t)BSZ * SEQ * DIM];
static __device__ __align__(256) __half g_wh[(size_t)4 * DIM * DIM];

// ---------------- helpers ----------------
__device__ __forceinline__ uint32_t smem_u32(const void* p) {
    uint32_t r;
    asm("{ .reg .u64 t; cvta.to.shared.u64 t, %1; cvt.u32.u64 %0, t; }" : "=r"(r) : "l"(p));
    return r;
}

__device__ __forceinline__ void cp16(uint32_t d, const void* g) {
    asm volatile("cp.async.cg.shared.global [%0], [%1], 16;" :: "r"(d), "l"(g) : "memory");
}
#define CP_COMMIT() asm volatile("cp.async.commit_group;" ::: "memory")
#define CP_WAIT1()  asm volatile("cp.async.wait_group 1;" ::: "memory")

__device__ __forceinline__ void ldsm4(uint32_t* r, uint32_t a) {
    asm volatile("ldmatrix.sync.aligned.m8n8.x4.shared.b16 {%0,%1,%2,%3}, [%4];"
                 : "=r"(r[0]), "=r"(r[1]), "=r"(r[2]), "=r"(r[3]) : "r"(a));
}

__device__ __forceinline__ void mma_16816(float* c, const uint32_t* a, const uint32_t* b) {
    asm volatile(
        "mma.sync.aligned.m16n8k16.row.col.f32.f16.f16.f32 "
        "{%0,%1,%2,%3}, {%4,%5,%6,%7}, {%8,%9}, {%0,%1,%2,%3};\n"
        : "+f"(c[0]), "+f"(c[1]), "+f"(c[2]), "+f"(c[3])
        : "r"(a[0]), "r"(a[1]), "r"(a[2]), "r"(a[3]),
          "r"(b[0]), "r"(b[1]));
}

__device__ __forceinline__ uint32_t pack_halves(__half lo, __half hi) {
    __half2 t = __halves2half2(lo, hi);
    return *reinterpret_cast<uint32_t*>(&t);
}

constexpr int BM = 128, BN = 128, BK = 32, PADH = 8;
constexpr float NEGBIG = -1e30f;
constexpr float QK_SCALE = 0.08838834764831845f;

// =====================================================================
//  gemm512: CTA tile 128x256, 512 threads, warp tile 32x64, BK=64,
//  3-stage cp.async pipeline, ldmatrix fragment loads.
//  C[m][n] = scale[n] * sum_k A[m][k] * B[n][k]   (A,B fp16 K-major)
//  grid.z selects among up to 3 (B, scale, C) problem instances.
// =====================================================================
constexpr int GP = 72;                          // smem pitch (halves) = 144B
constexpr int GA_ST = 128 * GP;                 // A stage halves
constexpr int GB_ST = 256 * GP;                 // B stage halves
constexpr int G_SMEM = 3 * (GA_ST + GB_ST) * 2; // 165888 bytes

struct GemmSet {
    const __half* B[3];
    const float*  s[3];
    float*        C[3];
};

__global__ void __launch_bounds__(512, 1) gemm512(
    const __half* __restrict__ A, GemmSet gs)
{
    extern __shared__ __half sm[];
    __half* As = sm;                 // [3][128][GP]
    __half* Bs = sm + 3 * GA_ST;     // [3][256][GP]

    const __half* Bw = gs.B[blockIdx.z];
    const float*  scale = gs.s[blockIdx.z];
    float*        C = gs.C[blockIdx.z];

    const int K = DIM;
    const int tid = threadIdx.x;
    const int warp = tid >> 5, lane = tid & 31;
    const int m0 = blockIdx.y * 128, n0 = blockIdx.x * 256;
    const int wm = (warp & 3) * 32, wn = (warp >> 2) * 64;
    const int gid = lane >> 2, t2 = (lane & 3) * 2;

    // ---- loader mapping: 16B chunks ----
    // A: 1024 chunks (c>>3 = row 0..127, c&7 = 16B sub), thread handles c=tid, tid+512
    // B: 2048 chunks, thread handles tid, +512, +1024, +1536
    const int ar0 = tid >> 3, as0 = tid & 7;
    const int ar1 = (tid + 512) >> 3, as1 = tid & 7;
    uint32_t aDst[3][2];
    uint32_t bDst[3][4];
#pragma unroll
    for (int s = 0; s < 3; s++) {
        aDst[s][0] = smem_u32(As + (size_t)s * GA_ST + ar0 * GP + as0 * 8);
        aDst[s][1] = smem_u32(As + (size_t)s * GA_ST + ar1 * GP + as1 * 8);
#pragma unroll
        for (int j = 0; j < 4; j++) {
            const int c = tid + j * 512;
            bDst[s][j] = smem_u32(Bs + (size_t)s * GB_ST + (c >> 3) * GP + (c & 7) * 8);
        }
    }
    const __half* Ag0 = A + (size_t)(m0 + ar0) * K + as0 * 8;
    const __half* Ag1 = A + (size_t)(m0 + ar1) * K + as1 * 8;
    const __half* Bg[4];
#pragma unroll
    for (int j = 0; j < 4; j++) {
        const int c = tid + j * 512;
        Bg[j] = Bw + (size_t)(n0 + (c >> 3)) * K + (c & 7) * 8;
    }

    // ---- fragment (ldmatrix) lane offsets ----
    const int a_r = (lane & 7) + ((lane >> 3) & 1) * 8;
    const int a_c = ((lane >> 4) & 1) * 8;
    const int b_r = (lane & 7) + ((lane >> 4) & 1) * 8;
    const int b_c = ((lane >> 3) & 1) * 8;

    uint32_t aFrag[3], bFrag[3];
#pragma unroll
    for (int s = 0; s < 3; s++) {
        aFrag[s] = smem_u32(As + (size_t)s * GA_ST + (wm + a_r) * GP + a_c);
        bFrag[s] = smem_u32(Bs + (size_t)s * GB_ST + (wn + b_r) * GP + b_c);
    }

    float c[2][8][4];
#pragma unroll
    for (int mt = 0; mt < 2; mt++)
#pragma unroll
        for (int nt = 0; nt < 8; nt++)
#pragma unroll
            for (int r = 0; r < 4; r++) c[mt][nt][r] = 0.f;

    // ---- prologue: stages 0,1 ----
#pragma unroll
    for (int s = 0; s < 2; s++) {
        cp16(aDst[s][0], Ag0 + s * 64);
        cp16(aDst[s][1], Ag1 + s * 64);
#pragma unroll
        for (int j = 0; j < 4; j++) cp16(bDst[s][j], Bg[j] + s * 64);
        CP_COMMIT();
    }

    const int NK = K / 64;  // 64
    int s = 0;
    for (int kt = 0; kt < NK; kt++) {
        CP_WAIT1();
        __syncthreads();

        if (kt + 2 < NK) {
            int sn = s + 2; if (sn >= 3) sn -= 3;
            const int ko = (kt + 2) * 64;
            cp16(aDst[sn][0], Ag0 + ko);
            cp16(aDst[sn][1], Ag1 + ko);
#pragma unroll
            for (int j = 0; j < 4; j++) cp16(bDst[sn][j], Bg[j] + ko);
        }
        CP_COMMIT();

        const uint32_t aB = aFrag[s], bB = bFrag[s];
#pragma unroll
        for (int kk = 0; kk < 64; kk += 16) {
            uint32_t af[2][4], bf[4][4];
            ldsm4(af[0], aB + kk * 2);
            ldsm4(af[1], aB + (16 * GP + kk) * 2);
#pragma unroll
            for (int p = 0; p < 4; p++)
                ldsm4(bf[p], bB + (p * 16 * GP + kk) * 2);
#pragma unroll
            for (int mt = 0; mt < 2; mt++)
#pragma unroll
                for (int nt = 0; nt < 8; nt++)
                    mma_16816(c[mt][nt], af[mt], &bf[nt >> 1][(nt & 1) * 2]);
        }
        if (++s == 3) s = 0;
    }

    // ---- epilogue ----
#pragma unroll
    for (int nt = 0; nt < 8; nt++) {
        const int col = n0 + wn + nt * 8 + t2;
        const float s0 = __ldg(scale + col), s1 = __ldg(scale + col + 1);
#pragma unroll
        for (int mt = 0; mt < 2; mt++) {
            const int row = m0 + wm + mt * 16 + gid;
            C[(size_t)row * DIM + col]           = c[mt][nt][0] * s0;
            C[(size_t)row * DIM + col + 1]       = c[mt][nt][1] * s1;
            C[(size_t)(row + 8) * DIM + col]     = c[mt][nt][2] * s0;
            C[(size_t)(row + 8) * DIM + col + 1] = c[mt][nt][3] * s1;
        }
    }
}

// =====================================================================
// conversion kernels
// =====================================================================
__global__ void conv_w_kernel(const int4* __restrict__ w, __half* __restrict__ out, int n4)
{
    for (int i = blockIdx.x * blockDim.x + threadIdx.x; i < n4; i += gridDim.x * blockDim.x) {
        const int4 v = w[i];
        __half2 h0 = __halves2half2(__int2half_rn(v.x), __int2half_rn(v.y));
        __half2 h1 = __halves2half2(__int2half_rn(v.z), __int2half_rn(v.w));
        uint2 u;
        u.x = *reinterpret_cast<uint32_t*>(&h0);
        u.y = *reinterpret_cast<uint32_t*>(&h1);
        ((uint2*)out)[i] = u;
    }
}

__global__ void conv_x_kernel(const float4* __restrict__ x, __half* __restrict__ out, int n4)
{
    for (int i = blockIdx.x * blockDim.x + threadIdx.x; i < n4; i += gridDim.x * blockDim.x) {
        const float4 v = x[i];
        __half2 h0 = __floats2half2_rn(v.x, v.y);
        __half2 h1 = __floats2half2_rn(v.z, v.w);
        uint2 u;
        u.x = *reinterpret_cast<uint32_t*>(&h0);
        u.y = *reinterpret_cast<uint32_t*>(&h1);
        ((uint2*)out)[i] = u;
    }
}

// =====================================================================
// RoPE (vectorized) + cache scatter. One block per (b,s), 256 threads.
// unit u (0..511): 8 consecutive floats = 4 rotary pairs.
// =====================================================================
__global__ __launch_bounds__(256) void rope_cache_kernel(
    const float* __restrict__ fcos, const float* __restrict__ fsin,
    const int* __restrict__ idx,
    float* __restrict__ cacheK, float* __restrict__ cacheV)
{
    const int bs = blockIdx.x;
    const int b = bs >> 9, sq = bs & 511;
    const int t = idx[sq];
    const size_t rbase = (size_t)bs * DIM;
    const size_t cbase = ((size_t)(b * MAXSEQ + t)) * DIM;

    for (int u = threadIdx.x; u < 512; u += 256) {
        const int off = u * 8;             // float offset within row
        const int p = (u & 15) * 4;        // pair index within head (0..60)
        const float4 c0 = *(const float4*)(fcos + sq * 64 + p);  // 4 cos
        const float4 s0 = *(const float4*)(fsin + sq * 64 + p);

        float4 q0 = *(float4*)(g_q + rbase + off);
        float4 q1 = *(float4*)(g_q + rbase + off + 4);
        float4 k0 = *(float4*)(g_k + rbase + off);
        float4 k1 = *(float4*)(g_k + rbase + off + 4);

        float4 qo0, qo1, ko0, ko1;
        qo0.x = q0.x * c0.x - q0.y * s0.x;  qo0.y = q0.x * s0.x + q0.y * c0.x;
        qo0.z = q0.z * c0.y - q0.w * s0.y;  qo0.w = q0.z * s0.y + q0.w * c0.y;
        qo1.x = q1.x * c0.z - q1.y * s0.z;  qo1.y = q1.x * s0.z + q1.y * c0.z;
        qo1.z = q1.z * c0.w - q1.w * s0.w;  qo1.w = q1.z * s0.w + q1.w * c0.w;
        ko0.x = k0.x * c0.x - k0.y * s0.x;  ko0.y = k0.x * s0.x + k0.y * c0.x;
        ko0.z = k0.z * c0.y - k0.w * s0.y;  ko0.w = k0.z * s0.y + k0.w * c0.y;
        ko1.x = k1.x * c0.z - k1.y * s0.z;  ko1.y = k1.x * s0.z + k1.y * c0.z;
        ko1.z = k1.z * c0.w - k1.w * s0.w;  ko1.w = k1.z * s0.w + k1.w * c0.w;

        *(float4*)(g_q + rbase + off)     = qo0;
        *(float4*)(g_q + rbase + off + 4) = qo1;
        *(float4*)(g_k + rbase + off)     = ko0;
        *(float4*)(g_k + rbase + off + 4) = ko1;
        *(float4*)(cacheK + cbase + off)     = ko0;
        *(float4*)(cacheK + cbase + off + 4) = ko1;
        *(float4*)(cacheV + cbase + off)     = *(float4*)(g_v + rbase + off);
        *(float4*)(cacheV + cbase + off + 4) = *(float4*)(g_v + rbase + off + 4);
    }
}

__global__ void zero_tail_kernel(float4* __restrict__ ck, float4* __restrict__ cv)
{
    const int perB = 1536 * 1024;
    const int n = BSZ * perB;
    const float4 z = make_float4(0.f, 0.f, 0.f, 0.f);
    for (int i = blockIdx.x * blockDim.x + threadIdx.x; i < n; i += gridDim.x * blockDim.x) {
        const int b = i / perB, r = i - b * perB;
        const size_t off = ((size_t)b * MAXSEQ + SEQ) * (DIM / 4) + r;
        ck[off] = z;
        cv[off] = z;
    }
}

// =====================================================================
// QK^T scores with causal mask (HMMA, unchanged)
// =====================================================================
__global__ __launch_bounds__(256) void gemm_qk_kernel()
{
    const int z = blockIdx.z;
    const int b = z >> 5, h = z & 31;
    const int m0 = blockIdx.y * BM, n0 = blockIdx.x * BN;
    float* Cp = g_sc + (size_t)z * SEQ * SEQ;

    if (n0 >= m0 + BM) {
        for (int i = threadIdx.x; i < BM * BN; i += 256)
            Cp[(size_t)(m0 + i / BN) * SEQ + n0 + (i % BN)] = NEGBIG;
        return;
    }

    const float* Aq = g_q + (size_t)b * SEQ * DIM + (size_t)h * HD;
    const float* Bk = g_k + (size_t)b * SEQ * DIM + (size_t)h * HD;

    __shared__ __half As[2][BM][BK + PADH];
    __shared__ __half Bs[2][BN][BK + PADH];

    const int tid  = threadIdx.x;
    const int warp = tid >> 5, lane = tid & 31;
    const int gid  = lane >> 2, t2 = (lane & 3) * 2;
    const int wm   = (warp & 1) * 64, wn = (warp >> 1) * 32;
    const int lrow = tid >> 3, lcol = (tid & 7) * 4;

    float c[4][4][4];
#pragma unroll
    for (int mt = 0; mt < 4; mt++)
#pragma unroll
        for (int nt = 0; nt < 4; nt++)
#pragma unroll
            for (int r = 0; r < 4; r++) c[mt][nt][r] = 0.f;

    float4 aN[4], bN[4];
#pragma unroll
    for (int i = 0; i < 4; i++) {
        aN[i] = *(const float4*)(Aq + (size_t)(m0 + lrow + 32 * i) * DIM + lcol);
        bN[i] = *(const float4*)(Bk + (size_t)(n0 + lrow + 32 * i) * DIM + lcol);
    }
#pragma unroll
    for (int i = 0; i < 4; i++) {
        __half2* pa = (__half2*)&As[0][lrow + 32 * i][lcol];
        pa[0] = __floats2half2_rn(aN[i].x, aN[i].y);
        pa[1] = __floats2half2_rn(aN[i].z, aN[i].w);
        __half2* pb = (__half2*)&Bs[0][lrow + 32 * i][lcol];
        pb[0] = __floats2half2_rn(bN[i].x, bN[i].y);
        pb[1] = __floats2half2_rn(bN[i].z, bN[i].w);
    }
    __syncthreads();

    const int nk = HD / BK;  // 4
    for (int kt = 0; kt < nk; kt++) {
        const int buf = kt & 1;
        const bool has_next = (kt + 1 < nk);
        if (has_next) {
#pragma unroll
            for (int i = 0; i < 4; i++) {
                aN[i] = *(const float4*)(Aq + (size_t)(m0 + lrow + 32 * i) * DIM + (kt + 1) * BK + lcol);
                bN[i] = *(const float4*)(Bk + (size_t)(n0 + lrow + 32 * i) * DIM + (kt + 1) * BK + lcol);
            }
        }
#pragma unroll
        for (int kk = 0; kk < BK; kk += 16) {
            uint32_t af[4][4], bf[4][2];
#pragma unroll
            for (int mt = 0; mt < 4; mt++) {
                const int r = wm + mt * 16 + gid;
                af[mt][0] = *(const uint32_t*)&As[buf][r][kk + t2];
                af[mt][1] = *(const uint32_t*)&As[buf][r + 8][kk + t2];
                af[mt][2] = *(const uint32_t*)&As[buf][r][kk + t2 + 8];
                af[mt][3] = *(const uint32_t*)&As[buf][r + 8][kk + t2 + 8];
            }
#pragma unroll
            for (int nt = 0; nt < 4; nt++) {
                const int rn = wn + nt * 8 + gid;
                bf[nt][0] = *(const uint32_t*)&Bs[buf][rn][kk + t2];
                bf[nt][1] = *(const uint32_t*)&Bs[buf][rn][kk + t2 + 8];
            }
#pragma unroll
            for (int mt = 0; mt < 4; mt++)
#pragma unroll
                for (int nt = 0; nt < 4; nt++) mma_16816(c[mt][nt], af[mt], bf[nt]);
        }
        if (has_next) {
#pragma unroll
            for (int i = 0; i < 4; i++) {
                __half2* pa = (__half2*)&As[buf ^ 1][lrow + 32 * i][lcol];
                pa[0] = __floats2half2_rn(aN[i].x, aN[i].y);
                pa[1] = __floats2half2_rn(aN[i].z, aN[i].w);
                __half2* pb = (__half2*)&Bs[buf ^ 1][lrow + 32 * i][lcol];
                pb[0] = __floats2half2_rn(bN[i].x, bN[i].y);
                pb[1] = __floats2half2_rn(bN[i].z, bN[i].w);
            }
        }
        __syncthreads();
    }

#pragma unroll
    for (int mt = 0; mt < 4; mt++)
#pragma unroll
        for (int nt = 0; nt < 4; nt++) {
            const int row = m0 + wm + mt * 16 + gid;
            const int col = n0 + wn + nt * 8 + t2;
            float v0 = c[mt][nt][0] * QK_SCALE; if (col > row)         v0 = NEGBIG;
            float v1 = c[mt][nt][1] * QK_SCALE; if (col + 1 > row)     v1 = NEGBIG;
            float v2 = c[mt][nt][2] * QK_SCALE; if (col > row + 8)     v2 = NEGBIG;
            float v3 = c[mt][nt][3] * QK_SCALE; if (col + 1 > row + 8) v3 = NEGBIG;
            Cp[(size_t)row * SEQ + col]           = v0;
            Cp[(size_t)row * SEQ + col + 1]       = v1;
            Cp[(size_t)(row + 8) * SEQ + col]     = v2;
            Cp[(size_t)(row + 8) * SEQ + col + 1] = v3;
        }
}

// =====================================================================
// Row softmax
// =====================================================================
__global__ __launch_bounds__(256) void softmax_kernel()
{
    const int row  = blockIdx.x * 8 + (threadIdx.x >> 5);
    const int lane = threadIdx.x & 31;
    float* p = g_sc + (size_t)row * SEQ;

    float4 v[4];
    float mx = -3.4e38f;
#pragma unroll
    for (int i = 0; i < 4; i++) {
        v[i] = *(float4*)(p + lane * 4 + i * 128);
        mx = fmaxf(mx, fmaxf(fmaxf(v[i].x, v[i].y), fmaxf(v[i].z, v[i].w)));
    }
#pragma unroll
    for (int o = 16; o > 0; o >>= 1) mx = fmaxf(mx, __shfl_xor_sync(0xffffffffu, mx, o));

    float s = 0.f;
#pragma unroll
    for (int i = 0; i < 4; i++) {
        v[i].x = __expf(v[i].x - mx);
        v[i].y = __expf(v[i].y - mx);
        v[i].z = __expf(v[i].z - mx);
        v[i].w = __expf(v[i].w - mx);
        s += v[i].x + v[i].y + v[i].z + v[i].w;
    }
#pragma unroll
    for (int o = 16; o > 0; o >>= 1) s += __shfl_xor_sync(0xffffffffu, s, o);
    const float r = 1.f / s;
#pragma unroll
    for (int i = 0; i < 4; i++) {
        v[i].x *= r; v[i].y *= r; v[i].z *= r; v[i].w *= r;
        *(float4*)(p + lane * 4 + i * 128) = v[i];
    }
}

// =====================================================================
// PV -> g_attnh (fp16)
// =====================================================================
__global__ __launch_bounds__(256) void gemm_pv_kernel()
{
    const int z = blockIdx.z;
    const int b = z >> 5, h = z & 31;
    const int m0 = blockIdx.y * BM;
    const float* Ap = g_sc + (size_t)z * SEQ * SEQ;
    const float* Vp = g_v + (size_t)b * SEQ * DIM + (size_t)h * HD;

    __shared__ __half As[2][BM][BK + PADH];
    __shared__ __half Bs[2][BK][BN + PADH];

    const int tid  = threadIdx.x;
    const int warp = tid >> 5, lane = tid & 31;
    const int gid  = lane >> 2, t2 = (lane & 3) * 2;
    const int wm   = (warp & 1) * 64, wn = (warp >> 1) * 32;
    const int lrow = tid >> 3, lcol = (tid & 7) * 4;
    const int krow = tid >> 5, kcol = (tid & 31) * 4;

    float c[4][4][4];
#pragma unroll
    for (int mt = 0; mt < 4; mt++)
#pragma unroll
        for (int nt = 0; nt < 4; nt++)
#pragma unroll
            for (int r = 0; r < 4; r++) c[mt][nt][r] = 0.f;

    float4 aN[4], bN[4];
#pragma unroll
    for (int i = 0; i < 4; i++) {
        aN[i] = *(const float4*)(Ap + (size_t)(m0 + lrow + 32 * i) * SEQ + lcol);
        bN[i] = *(const float4*)(Vp + (size_t)(krow + 8 * i) * DIM + kcol);
    }
#pragma unroll
    for (int i = 0; i < 4; i++) {
        __half2* pa = (__half2*)&As[0][lrow + 32 * i][lcol];
        pa[0] = __floats2half2_rn(aN[i].x, aN[i].y);
        pa[1] = __floats2half2_rn(aN[i].z, aN[i].w);
        __half2* pb = (__half2*)&Bs[0][krow + 8 * i][kcol];
        pb[0] = __floats2half2_rn(bN[i].x, bN[i].y);
        pb[1] = __floats2half2_rn(bN[i].z, bN[i].w);
    }
    __syncthreads();

    const int nk = SEQ / BK;  // 16
    for (int kt = 0; kt < nk; kt++) {
        const int buf = kt & 1;
        const bool has_next = (kt + 1 < nk);
        if (has_next) {
#pragma unroll
            for (int i = 0; i < 4; i++) {
                aN[i] = *(const float4*)(Ap + (size_t)(m0 + lrow + 32 * i) * SEQ + (kt + 1) * BK + lcol);
                bN[i] = *(const float4*)(Vp + (size_t)((kt + 1) * BK + krow + 8 * i) * DIM + kcol);
            }
        }
#pragma unroll
        for (int kk = 0; kk < BK; kk += 16) {
            uint32_t af[4][4], bf[4][2];
#pragma unroll
            for (int mt = 0; mt < 4; mt++) {
                const int r = wm + mt * 16 + gid;
                af[mt][0] = *(const uint32_t*)&As[buf][r][kk + t2];
                af[mt][1] = *(const uint32_t*)&As[buf][r + 8][kk + t2];
                af[mt][2] = *(const uint32_t*)&As[buf][r][kk + t2 + 8];
                af[mt][3] = *(const uint32_t*)&As[buf][r + 8][kk + t2 + 8];
            }
#pragma unroll
            for (int nt = 0; nt < 4; nt++) {
                const int nn = wn + nt * 8 + gid;
                bf[nt][0] = pack_halves(Bs[buf][kk + t2][nn],     Bs[buf][kk + t2 + 1][nn]);
                bf[nt][1] = pack_halves(Bs[buf][kk + t2 + 8][nn], Bs[buf][kk + t2 + 9][nn]);
            }
#pragma unroll
            for (int mt = 0; mt < 4; mt++)
#pragma unroll
                for (int nt = 0; nt < 4; nt++) mma_16816(c[mt][nt], af[mt], bf[nt]);
        }
        if (has_next) {
#pragma unroll
            for (int i = 0; i < 4; i++) {
                __half2* pa = (__half2*)&As[buf ^ 1][lrow + 32 * i][lcol];
                pa[0] = __floats2half2_rn(aN[i].x, aN[i].y);
                pa[1] = __floats2half2_rn(aN[i].z, aN[i].w);
                __half2* pb = (__half2*)&Bs[buf ^ 1][krow + 8 * i][kcol];
                pb[0] = __floats2half2_rn(bN[i].x, bN[i].y);
                pb[1] = __floats2half2_rn(bN[i].z, bN[i].w);
            }
        }
        __syncthreads();
    }

#pragma unroll
    for (int mt = 0; mt < 4; mt++)
#pragma unroll
        for (int nt = 0; nt < 4; nt++) {
            const int row = m0 + wm + mt * 16 + gid;
            const int col = wn + nt * 8 + t2;
            __half* d0 = g_attnh + (size_t)(b * SEQ + row) * DIM + (size_t)h * HD;
            __half* d1 = g_attnh + (size_t)(b * SEQ + row + 8) * DIM + (size_t)h * HD;
            *(__half2*)(d0 + col) = __floats2half2_rn(c[mt][nt][0], c[mt][nt][1]);
            *(__half2*)(d1 + col) = __floats2half2_rn(c[mt][nt][2], c[mt][nt][3]);
        }
}

// =====================================================================
extern "C" void kernel_launch(void* const* d_in, const int* in_sizes, int n_in,
                              void* d_out, int out_size)
{
    (void)in_sizes; (void)n_in; (void)out_size;
    const float* x    = (const float*)d_in[0];
    const float* fcos = (const float*)d_in[1];
    const float* fsin = (const float*)d_in[2];
    const int*   idx  = (const int*)d_in[4];
    const int*   wq   = (const int*)d_in[7];
    const float* sq   = (const float*)d_in[8];
    const int*   wk   = (const int*)d_in[9];
    const float* sk   = (const float*)d_in[10];
    const int*   wv   = (const int*)d_in[11];
    const float* sv   = (const float*)d_in[12];
    const int*   wo   = (const int*)d_in[13];
    const float* so   = (const float*)d_in[14];

    float* out    = (float*)d_out;
    float* cacheK = out + (size_t)BSZ * SEQ * DIM;
    float* cacheV = cacheK + (size_t)BSZ * MAXSEQ * NHEADS * HD;

    float  *pq = nullptr, *pk = nullptr, *pv = nullptr;
    __half *pxh = nullptr, *pwh = nullptr, *pah = nullptr;
    cudaGetSymbolAddress((void**)&pq, g_q);
    cudaGetSymbolAddress((void**)&pk, g_k);
    cudaGetSymbolAddress((void**)&pv, g_v);
    cudaGetSymbolAddress((void**)&pxh, g_xh);
    cudaGetSymbolAddress((void**)&pwh, g_wh);
    cudaGetSymbolAddress((void**)&pah, g_attnh);

    cudaFuncSetAttribute(gemm512, cudaFuncAttributeMaxDynamicSharedMemorySize, G_SMEM);

    const size_t W = (size_t)DIM * DIM;

    // 1) conversions (fp16 once; weights are exact integers in fp16)
    conv_x_kernel<<<1184, 256>>>((const float4*)x, pxh, (int)(BSZ * SEQ * DIM / 4));
    conv_w_kernel<<<2368, 256>>>((const int4*)wq, pwh + 0 * W, (int)(W / 4));
    conv_w_kernel<<<2368, 256>>>((const int4*)wk, pwh + 1 * W, (int)(W / 4));
    conv_w_kernel<<<2368, 256>>>((const int4*)wv, pwh + 2 * W, (int)(W / 4));
    conv_w_kernel<<<2368, 256>>>((const int4*)wo, pwh + 3 * W, (int)(W / 4));

    // 2) fused QKV projection (one launch, grid.z = 3)
    GemmSet qkv;
    qkv.B[0] = pwh + 0 * W; qkv.s[0] = sq; qkv.C[0] = pq;
    qkv.B[1] = pwh + 1 * W; qkv.s[1] = sk; qkv.C[1] = pk;
    qkv.B[2] = pwh + 2 * W; qkv.s[2] = sv; qkv.C[2] = pv;
    gemm512<<<dim3(DIM / 256, (BSZ * SEQ) / 128, 3), 512, G_SMEM>>>(pxh, qkv);

    // 3) RoPE + cache scatter + tail zero
    rope_cache_kernel<<<BSZ * SEQ, 256>>>(fcos, fsin, idx, cacheK, cacheV);
    zero_tail_kernel<<<2048, 256>>>((float4*)cacheK, (float4*)cacheV);

    // 4) attention middle
    gemm_qk_kernel<<<dim3(SEQ / BN, SEQ / BM, BSZ * NHEADS), 256>>>();
    softmax_kernel<<<(BSZ * NHEADS * SEQ) / 8, 256>>>();
    gemm_pv_kernel<<<dim3(1, SEQ / BM, BSZ * NHEADS), 256>>>();

    // 5) output projection
    GemmSet og;
    og.B[0] = pwh + 3 * W; og.s[0] = so; og.C[0] = out;
    og.B[1] = og.B[0]; og.s[1] = og.s[0]; og.C[1] = og.C[0];
    og.B[2] = og.B[0]; og.s[2] = og.s[0]; og.C[2] = og.C[0];
    gemm512<<<dim3(DIM / 256, (BSZ * SEQ) / 128, 1), 512, G_SMEM>>>(pah, og);
}

// round 6
// speedup vs baseline: 1.5224x; 1.0819x over previous
#include <cuda_runtime.h>
#include <cuda_fp16.h>
#include <stdint.h>

#define DIM 4096
#define NHEADS 32
#define HD 128
#define BSZ 4
#define SEQ 512
#define MAXSEQ 2048

// ---------------- scratch ----------------
static __device__ __align__(256) float  g_q[(size_t)BSZ * SEQ * DIM];
static __device__ __align__(256) float  g_k[(size_t)BSZ * SEQ * DIM];
static __device__ __align__(256) float  g_v[(size_t)BSZ * SEQ * DIM];
static __device__ __align__(256) __half g_xh[(size_t)BSZ * SEQ * DIM];
static __device__ __align__(256) __half g_attnh[(size_t)BSZ * SEQ * DIM];
static __device__ __align__(256) __half g_wh[(size_t)4 * DIM * DIM];
static __device__ __align__(256) __half g_qh[(size_t)BSZ * SEQ * DIM];
static __device__ __align__(256) __half g_kh[(size_t)BSZ * SEQ * DIM];
static __device__ __align__(256) __half g_vh[(size_t)BSZ * SEQ * DIM];

// ---------------- helpers ----------------
__device__ __forceinline__ uint32_t smem_u32(const void* p) {
    uint32_t r;
    asm("{ .reg .u64 t; cvta.to.shared.u64 t, %1; cvt.u32.u64 %0, t; }" : "=r"(r) : "l"(p));
    return r;
}

__device__ __forceinline__ void cp16(uint32_t d, const void* g) {
    asm volatile("cp.async.cg.shared.global [%0], [%1], 16;" :: "r"(d), "l"(g) : "memory");
}
#define CP_COMMIT() asm volatile("cp.async.commit_group;" ::: "memory")
#define CP_WAIT1()  asm volatile("cp.async.wait_group 1;" ::: "memory")
#define CP_WAIT0()  asm volatile("cp.async.wait_group 0;" ::: "memory")

__device__ __forceinline__ void ldsm4(uint32_t* r, uint32_t a) {
    asm volatile("ldmatrix.sync.aligned.m8n8.x4.shared.b16 {%0,%1,%2,%3}, [%4];"
                 : "=r"(r[0]), "=r"(r[1]), "=r"(r[2]), "=r"(r[3]) : "r"(a));
}
__device__ __forceinline__ void ldsm4t(uint32_t* r, uint32_t a) {
    asm volatile("ldmatrix.sync.aligned.m8n8.x4.trans.shared.b16 {%0,%1,%2,%3}, [%4];"
                 : "=r"(r[0]), "=r"(r[1]), "=r"(r[2]), "=r"(r[3]) : "r"(a));
}

__device__ __forceinline__ void mma_16816(float* c, const uint32_t* a, const uint32_t* b) {
    asm volatile(
        "mma.sync.aligned.m16n8k16.row.col.f32.f16.f16.f32 "
        "{%0,%1,%2,%3}, {%4,%5,%6,%7}, {%8,%9}, {%0,%1,%2,%3};\n"
        : "+f"(c[0]), "+f"(c[1]), "+f"(c[2]), "+f"(c[3])
        : "r"(a[0]), "r"(a[1]), "r"(a[2]), "r"(a[3]),
          "r"(b[0]), "r"(b[1]));
}

__device__ __forceinline__ uint32_t pack2f(float a, float b) {
    __half2 t = __floats2half2_rn(a, b);
    return *reinterpret_cast<uint32_t*>(&t);
}

constexpr float QK_SCALE = 0.08838834764831845f;  // 1/sqrt(128)

// =====================================================================
//  gemm512: 128x256 tile, 512 threads, BK=64, 3-stage cp.async, ldmatrix.
//  C[m][n] = scale[n]*sum_k A[m][k]*B[n][k]
// =====================================================================
constexpr int GP = 72;
constexpr int GA_ST = 128 * GP;
constexpr int GB_ST = 256 * GP;
constexpr int G_SMEM = 3 * (GA_ST + GB_ST) * 2;

struct GemmSet {
    const __half* B[3];
    const float*  s[3];
    float*        C[3];
};

__global__ void __launch_bounds__(512, 1) gemm512(
    const __half* __restrict__ A, GemmSet gs)
{
    extern __shared__ __half sm[];
    __half* As = sm;
    __half* Bs = sm + 3 * GA_ST;

    const __half* Bw = gs.B[blockIdx.z];
    const float*  scale = gs.s[blockIdx.z];
    float*        C = gs.C[blockIdx.z];

    const int K = DIM;
    const int tid = threadIdx.x;
    const int warp = tid >> 5, lane = tid & 31;
    const int m0 = blockIdx.y * 128, n0 = blockIdx.x * 256;
    const int wm = (warp & 3) * 32, wn = (warp >> 2) * 64;
    const int gid = lane >> 2, t2 = (lane & 3) * 2;

    const int ar0 = tid >> 3, as0 = tid & 7;
    const int ar1 = (tid + 512) >> 3, as1 = tid & 7;
    uint32_t aDst[3][2];
    uint32_t bDst[3][4];
#pragma unroll
    for (int s = 0; s < 3; s++) {
        aDst[s][0] = smem_u32(As + (size_t)s * GA_ST + ar0 * GP + as0 * 8);
        aDst[s][1] = smem_u32(As + (size_t)s * GA_ST + ar1 * GP + as1 * 8);
#pragma unroll
        for (int j = 0; j < 4; j++) {
            const int c = tid + j * 512;
            bDst[s][j] = smem_u32(Bs + (size_t)s * GB_ST + (c >> 3) * GP + (c & 7) * 8);
        }
    }
    const __half* Ag0 = A + (size_t)(m0 + ar0) * K + as0 * 8;
    const __half* Ag1 = A + (size_t)(m0 + ar1) * K + as1 * 8;
    const __half* Bg[4];
#pragma unroll
    for (int j = 0; j < 4; j++) {
        const int c = tid + j * 512;
        Bg[j] = Bw + (size_t)(n0 + (c >> 3)) * K + (c & 7) * 8;
    }

    const int a_r = (lane & 7) + ((lane >> 3) & 1) * 8;
    const int a_c = ((lane >> 4) & 1) * 8;
    const int b_r = (lane & 7) + ((lane >> 4) & 1) * 8;
    const int b_c = ((lane >> 3) & 1) * 8;

    uint32_t aFrag[3], bFrag[3];
#pragma unroll
    for (int s = 0; s < 3; s++) {
        aFrag[s] = smem_u32(As + (size_t)s * GA_ST + (wm + a_r) * GP + a_c);
        bFrag[s] = smem_u32(Bs + (size_t)s * GB_ST + (wn + b_r) * GP + b_c);
    }

    float c[2][8][4];
#pragma unroll
    for (int mt = 0; mt < 2; mt++)
#pragma unroll
        for (int nt = 0; nt < 8; nt++)
#pragma unroll
            for (int r = 0; r < 4; r++) c[mt][nt][r] = 0.f;

#pragma unroll
    for (int s = 0; s < 2; s++) {
        cp16(aDst[s][0], Ag0 + s * 64);
        cp16(aDst[s][1], Ag1 + s * 64);
#pragma unroll
        for (int j = 0; j < 4; j++) cp16(bDst[s][j], Bg[j] + s * 64);
        CP_COMMIT();
    }

    const int NK = K / 64;
    int s = 0;
    for (int kt = 0; kt < NK; kt++) {
        CP_WAIT1();
        __syncthreads();

        if (kt + 2 < NK) {
            int sn = s + 2; if (sn >= 3) sn -= 3;
            const int ko = (kt + 2) * 64;
            cp16(aDst[sn][0], Ag0 + ko);
            cp16(aDst[sn][1], Ag1 + ko);
#pragma unroll
            for (int j = 0; j < 4; j++) cp16(bDst[sn][j], Bg[j] + ko);
        }
        CP_COMMIT();

        const uint32_t aB = aFrag[s], bB = bFrag[s];
#pragma unroll
        for (int kk = 0; kk < 64; kk += 16) {
            uint32_t af[2][4], bf[4][4];
            ldsm4(af[0], aB + kk * 2);
            ldsm4(af[1], aB + (16 * GP + kk) * 2);
#pragma unroll
            for (int p = 0; p < 4; p++)
                ldsm4(bf[p], bB + (p * 16 * GP + kk) * 2);
#pragma unroll
            for (int mt = 0; mt < 2; mt++)
#pragma unroll
                for (int nt = 0; nt < 8; nt++)
                    mma_16816(c[mt][nt], af[mt], &bf[nt >> 1][(nt & 1) * 2]);
        }
        if (++s == 3) s = 0;
    }

#pragma unroll
    for (int nt = 0; nt < 8; nt++) {
        const int col = n0 + wn + nt * 8 + t2;
        const float s0 = __ldg(scale + col), s1 = __ldg(scale + col + 1);
#pragma unroll
        for (int mt = 0; mt < 2; mt++) {
            const int row = m0 + wm + mt * 16 + gid;
            C[(size_t)row * DIM + col]           = c[mt][nt][0] * s0;
            C[(size_t)row * DIM + col + 1]       = c[mt][nt][1] * s1;
            C[(size_t)(row + 8) * DIM + col]     = c[mt][nt][2] * s0;
            C[(size_t)(row + 8) * DIM + col + 1] = c[mt][nt][3] * s1;
        }
    }
}

// =====================================================================
// conversion kernels
// =====================================================================
__global__ void conv_w_kernel(const int4* __restrict__ w, __half* __restrict__ out, int n4)
{
    for (int i = blockIdx.x * blockDim.x + threadIdx.x; i < n4; i += gridDim.x * blockDim.x) {
        const int4 v = w[i];
        __half2 h0 = __halves2half2(__int2half_rn(v.x), __int2half_rn(v.y));
        __half2 h1 = __halves2half2(__int2half_rn(v.z), __int2half_rn(v.w));
        uint2 u;
        u.x = *reinterpret_cast<uint32_t*>(&h0);
        u.y = *reinterpret_cast<uint32_t*>(&h1);
        ((uint2*)out)[i] = u;
    }
}

__global__ void conv_x_kernel(const float4* __restrict__ x, __half* __restrict__ out, int n4)
{
    for (int i = blockIdx.x * blockDim.x + threadIdx.x; i < n4; i += gridDim.x * blockDim.x) {
        const float4 v = x[i];
        __half2 h0 = __floats2half2_rn(v.x, v.y);
        __half2 h1 = __floats2half2_rn(v.z, v.w);
        uint2 u;
        u.x = *reinterpret_cast<uint32_t*>(&h0);
        u.y = *reinterpret_cast<uint32_t*>(&h1);
        ((uint2*)out)[i] = u;
    }
}

// =====================================================================
// RoPE + cache scatter + fp16 q/k/v emission (q pre-scaled by 1/sqrt(hd))
// =====================================================================
__global__ __launch_bounds__(256) void rope_cache_kernel(
    const float* __restrict__ fcos, const float* __restrict__ fsin,
    const int* __restrict__ idx,
    float* __restrict__ cacheK, float* __restrict__ cacheV)
{
    const int bs = blockIdx.x;
    const int b = bs >> 9, sq = bs & 511;
    const int t = idx[sq];
    const size_t rbase = (size_t)bs * DIM;
    const size_t cbase = ((size_t)(b * MAXSEQ + t)) * DIM;

    for (int u = threadIdx.x; u < 512; u += 256) {
        const int off = u * 8;
        const int p = (u & 15) * 4;
        const float4 c0 = *(const float4*)(fcos + sq * 64 + p);
        const float4 s0 = *(const float4*)(fsin + sq * 64 + p);

        float4 q0 = *(float4*)(g_q + rbase + off);
        float4 q1 = *(float4*)(g_q + rbase + off + 4);
        float4 k0 = *(float4*)(g_k + rbase + off);
        float4 k1 = *(float4*)(g_k + rbase + off + 4);
        float4 v0 = *(float4*)(g_v + rbase + off);
        float4 v1 = *(float4*)(g_v + rbase + off + 4);

        float4 qo0, qo1, ko0, ko1;
        qo0.x = q0.x * c0.x - q0.y * s0.x;  qo0.y = q0.x * s0.x + q0.y * c0.x;
        qo0.z = q0.z * c0.y - q0.w * s0.y;  qo0.w = q0.z * s0.y + q0.w * c0.y;
        qo1.x = q1.x * c0.z - q1.y * s0.z;  qo1.y = q1.x * s0.z + q1.y * c0.z;
        qo1.z = q1.z * c0.w - q1.w * s0.w;  qo1.w = q1.z * s0.w + q1.w * c0.w;
        ko0.x = k0.x * c0.x - k0.y * s0.x;  ko0.y = k0.x * s0.x + k0.y * c0.x;
        ko0.z = k0.z * c0.y - k0.w * s0.y;  ko0.w = k0.z * s0.y + k0.w * c0.y;
        ko1.x = k1.x * c0.z - k1.y * s0.z;  ko1.y = k1.x * s0.z + k1.y * c0.z;
        ko1.z = k1.z * c0.w - k1.w * s0.w;  ko1.w = k1.z * s0.w + k1.w * c0.w;

        *(float4*)(cacheK + cbase + off)     = ko0;
        *(float4*)(cacheK + cbase + off + 4) = ko1;
        *(float4*)(cacheV + cbase + off)     = v0;
        *(float4*)(cacheV + cbase + off + 4) = v1;

        uint2 uq, uk, uv;
        uq.x = pack2f(qo0.x * QK_SCALE, qo0.y * QK_SCALE);
        uq.y = pack2f(qo0.z * QK_SCALE, qo0.w * QK_SCALE);
        *(uint2*)(g_qh + rbase + off) = uq;
        uq.x = pack2f(qo1.x * QK_SCALE, qo1.y * QK_SCALE);
        uq.y = pack2f(qo1.z * QK_SCALE, qo1.w * QK_SCALE);
        *(uint2*)(g_qh + rbase + off + 4) = uq;
        uk.x = pack2f(ko0.x, ko0.y); uk.y = pack2f(ko0.z, ko0.w);
        *(uint2*)(g_kh + rbase + off) = uk;
        uk.x = pack2f(ko1.x, ko1.y); uk.y = pack2f(ko1.z, ko1.w);
        *(uint2*)(g_kh + rbase + off + 4) = uk;
        uv.x = pack2f(v0.x, v0.y); uv.y = pack2f(v0.z, v0.w);
        *(uint2*)(g_vh + rbase + off) = uv;
        uv.x = pack2f(v1.x, v1.y); uv.y = pack2f(v1.z, v1.w);
        *(uint2*)(g_vh + rbase + off + 4) = uv;
    }
}

__global__ void zero_tail_kernel(float4* __restrict__ ck, float4* __restrict__ cv)
{
    const int perB = 1536 * 1024;
    const int n = BSZ * perB;
    const float4 z = make_float4(0.f, 0.f, 0.f, 0.f);
    for (int i = blockIdx.x * blockDim.x + threadIdx.x; i < n; i += gridDim.x * blockDim.x) {
        const int b = i / perB, r = i - b * perB;
        const size_t off = ((size_t)b * MAXSEQ + SEQ) * (DIM / 4) + r;
        ck[off] = z;
        cv[off] = z;
    }
}

// =====================================================================
// Flash attention (fixed K B-fragment addressing)
// =====================================================================
constexpr int FP = 136;
constexpr int F_TILE = 128 * FP;
constexpr int F_SMEM = 5 * F_TILE * 2;

__global__ __launch_bounds__(256) void flash_kernel()
{
    extern __shared__ __half sm[];
    __half* Qs = sm;
    __half* Ks = sm + F_TILE;
    __half* Vs = sm + 3 * F_TILE;

    const int qt = blockIdx.x;
    const int z  = blockIdx.y;
    const int b = z >> 5, h = z & 31;
    const int tid = threadIdx.x, warp = tid >> 5, lane = tid & 31;
    const int gid = lane >> 2, t2 = (lane & 3) * 2;

    const __half* Qg = g_qh + ((size_t)(b * SEQ + qt * 128)) * DIM + h * HD;
    const __half* Kg = g_kh + ((size_t)b * SEQ) * DIM + h * HD;
    const __half* Vg = g_vh + ((size_t)b * SEQ) * DIM + h * HD;

#pragma unroll
    for (int j = 0; j < 8; j++) {
        const int c = tid + j * 256;
        const int row = c >> 4, sub = (c & 15) * 8;
        cp16(smem_u32(Qs + row * FP + sub), Qg + (size_t)row * DIM + sub);
    }
    CP_COMMIT();
#pragma unroll
    for (int j = 0; j < 8; j++) {
        const int c = tid + j * 256;
        const int row = c >> 4, sub = (c & 15) * 8;
        cp16(smem_u32(Ks + row * FP + sub), Kg + (size_t)row * DIM + sub);
        cp16(smem_u32(Vs + row * FP + sub), Vg + (size_t)row * DIM + sub);
    }
    CP_COMMIT();
    CP_WAIT0();
    __syncthreads();

    // A-operand addressing (Q, and V-trans)
    const int fr = (lane & 7) + ((lane >> 3) & 1) * 8;
    const int fc = ((lane >> 4) & 1) * 8;
    // B-operand addressing (K) — matrix order {n0k0, n0k1, n1k0, n1k1}
    const int kb_r = (lane & 7) + ((lane >> 4) & 1) * 8;
    const int kb_c = ((lane >> 3) & 1) * 8;

    const uint32_t qB = smem_u32(Qs + (warp * 16 + fr) * FP + fc);

    float o[16][4];
#pragma unroll
    for (int nt = 0; nt < 16; nt++)
#pragma unroll
        for (int r = 0; r < 4; r++) o[nt][r] = 0.f;
    float m0 = -1e30f, m1 = -1e30f, l0 = 0.f, l1 = 0.f;

    for (int kt = 0; kt <= qt; kt++) {
        const int buf = kt & 1;

        if (kt < qt) {
            const __half* Kn = Kg + (size_t)(kt + 1) * 128 * DIM;
            const __half* Vn = Vg + (size_t)(kt + 1) * 128 * DIM;
            __half* Kd = Ks + (buf ^ 1) * F_TILE;
            __half* Vd = Vs + (buf ^ 1) * F_TILE;
#pragma unroll
            for (int j = 0; j < 8; j++) {
                const int c = tid + j * 256;
                const int row = c >> 4, sub = (c & 15) * 8;
                cp16(smem_u32(Kd + row * FP + sub), Kn + (size_t)row * DIM + sub);
                cp16(smem_u32(Vd + row * FP + sub), Vn + (size_t)row * DIM + sub);
            }
            CP_COMMIT();
        }

        const uint32_t kB = smem_u32(Ks + buf * F_TILE + kb_r * FP + kb_c);
        const uint32_t vB = smem_u32(Vs + buf * F_TILE + fr * FP + fc);

        float s[16][4];
#pragma unroll
        for (int nt = 0; nt < 16; nt++)
#pragma unroll
            for (int r = 0; r < 4; r++) s[nt][r] = 0.f;

#pragma unroll
        for (int kk = 0; kk < 8; kk++) {
            uint32_t a[4];
            ldsm4(a, qB + kk * 32);
#pragma unroll
            for (int p = 0; p < 8; p++) {
                uint32_t bk[4];
                ldsm4(bk, kB + (p * 16 * FP + kk * 16) * 2);
                mma_16816(s[2 * p],     a, bk);
                mma_16816(s[2 * p + 1], a, bk + 2);
            }
        }

        if (kt == qt) {
            const int r0 = warp * 16 + gid, r1 = r0 + 8;
#pragma unroll
            for (int nt = 0; nt < 16; nt++) {
                const int c0 = nt * 8 + t2;
                if (c0 > r0)     s[nt][0] = -1e30f;
                if (c0 + 1 > r0) s[nt][1] = -1e30f;
                if (c0 > r1)     s[nt][2] = -1e30f;
                if (c0 + 1 > r1) s[nt][3] = -1e30f;
            }
        }

        float mx0 = -1e30f, mx1 = -1e30f;
#pragma unroll
        for (int nt = 0; nt < 16; nt++) {
            mx0 = fmaxf(mx0, fmaxf(s[nt][0], s[nt][1]));
            mx1 = fmaxf(mx1, fmaxf(s[nt][2], s[nt][3]));
        }
        mx0 = fmaxf(mx0, __shfl_xor_sync(0xffffffffu, mx0, 1));
        mx0 = fmaxf(mx0, __shfl_xor_sync(0xffffffffu, mx0, 2));
        mx1 = fmaxf(mx1, __shfl_xor_sync(0xffffffffu, mx1, 1));
        mx1 = fmaxf(mx1, __shfl_xor_sync(0xffffffffu, mx1, 2));

        const float mn0 = fmaxf(m0, mx0), mn1 = fmaxf(m1, mx1);
        const float sc0 = __expf(m0 - mn0), sc1 = __expf(m1 - mn1);
        m0 = mn0; m1 = mn1;

        float sum0 = 0.f, sum1 = 0.f;
#pragma unroll
        for (int nt = 0; nt < 16; nt++) {
            s[nt][0] = __expf(s[nt][0] - mn0);
            s[nt][1] = __expf(s[nt][1] - mn0);
            s[nt][2] = __expf(s[nt][2] - mn1);
            s[nt][3] = __expf(s[nt][3] - mn1);
            sum0 += s[nt][0] + s[nt][1];
            sum1 += s[nt][2] + s[nt][3];
        }
        sum0 += __shfl_xor_sync(0xffffffffu, sum0, 1);
        sum0 += __shfl_xor_sync(0xffffffffu, sum0, 2);
        sum1 += __shfl_xor_sync(0xffffffffu, sum1, 1);
        sum1 += __shfl_xor_sync(0xffffffffu, sum1, 2);
        l0 = l0 * sc0 + sum0;
        l1 = l1 * sc1 + sum1;

#pragma unroll
        for (int nt = 0; nt < 16; nt++) {
            o[nt][0] *= sc0; o[nt][1] *= sc0;
            o[nt][2] *= sc1; o[nt][3] *= sc1;
        }

#pragma unroll
        for (int ks = 0; ks < 8; ks++) {
            uint32_t pa[4];
            pa[0] = pack2f(s[2 * ks][0],     s[2 * ks][1]);
            pa[1] = pack2f(s[2 * ks][2],     s[2 * ks][3]);
            pa[2] = pack2f(s[2 * ks + 1][0], s[2 * ks + 1][1]);
            pa[3] = pack2f(s[2 * ks + 1][2], s[2 * ks + 1][3]);
#pragma unroll
            for (int dp = 0; dp < 8; dp++) {
                uint32_t vb[4];
                ldsm4t(vb, vB + (ks * 16 * FP + dp * 16) * 2);
                mma_16816(o[2 * dp],     pa, vb);
                mma_16816(o[2 * dp + 1], pa, vb + 2);
            }
        }

        if (kt < qt) {
            CP_WAIT0();
            __syncthreads();
        }
    }

    const float i0 = 1.f / l0, i1 = 1.f / l1;
    const int r0 = qt * 128 + warp * 16 + gid;
    __half* O0 = g_attnh + (size_t)(b * SEQ + r0) * DIM + h * HD;
    __half* O1 = O0 + (size_t)8 * DIM;
#pragma unroll
    for (int nt = 0; nt < 16; nt++) {
        const int col = nt * 8 + t2;
        *(uint32_t*)(O0 + col) = pack2f(o[nt][0] * i0, o[nt][1] * i0);
        *(uint32_t*)(O1 + col) = pack2f(o[nt][2] * i1, o[nt][3] * i1);
    }
}

// =====================================================================
extern "C" void kernel_launch(void* const* d_in, const int* in_sizes, int n_in,
                              void* d_out, int out_size)
{
    (void)in_sizes; (void)n_in; (void)out_size;
    const float* x    = (const float*)d_in[0];
    const float* fcos = (const float*)d_in[1];
    const float* fsin = (const float*)d_in[2];
    const int*   idx  = (const int*)d_in[4];
    const int*   wq   = (const int*)d_in[7];
    const float* sq   = (const float*)d_in[8];
    const int*   wk   = (const int*)d_in[9];
    const float* sk   = (const float*)d_in[10];
    const int*   wv   = (const int*)d_in[11];
    const float* sv   = (const float*)d_in[12];
    const int*   wo   = (const int*)d_in[13];
    const float* so   = (const float*)d_in[14];

    float* out    = (float*)d_out;
    float* cacheK = out + (size_t)BSZ * SEQ * DIM;
    float* cacheV = cacheK + (size_t)BSZ * MAXSEQ * NHEADS * HD;

    float  *pq = nullptr, *pk = nullptr, *pv = nullptr;
    __half *pxh = nullptr, *pwh = nullptr, *pah = nullptr;
    cudaGetSymbolAddress((void**)&pq, g_q);
    cudaGetSymbolAddress((void**)&pk, g_k);
    cudaGetSymbolAddress((void**)&pv, g_v);
    cudaGetSymbolAddress((void**)&pxh, g_xh);
    cudaGetSymbolAddress((void**)&pwh, g_wh);
    cudaGetSymbolAddress((void**)&pah, g_attnh);

    cudaFuncSetAttribute(gemm512, cudaFuncAttributeMaxDynamicSharedMemorySize, G_SMEM);
    cudaFuncSetAttribute(flash_kernel, cudaFuncAttributeMaxDynamicSharedMemorySize, F_SMEM);

    const size_t W = (size_t)DIM * DIM;

    // 1) conversions
    conv_x_kernel<<<1184, 256>>>((const float4*)x, pxh, (int)(BSZ * SEQ * DIM / 4));
    conv_w_kernel<<<2368, 256>>>((const int4*)wq, pwh + 0 * W, (int)(W / 4));
    conv_w_kernel<<<2368, 256>>>((const int4*)wk, pwh + 1 * W, (int)(W / 4));
    conv_w_kernel<<<2368, 256>>>((const int4*)wv, pwh + 2 * W, (int)(W / 4));
    conv_w_kernel<<<2368, 256>>>((const int4*)wo, pwh + 3 * W, (int)(W / 4));

    // 2) fused QKV projection
    GemmSet qkv;
    qkv.B[0] = pwh + 0 * W; qkv.s[0] = sq; qkv.C[0] = pq;
    qkv.B[1] = pwh + 1 * W; qkv.s[1] = sk; qkv.C[1] = pk;
    qkv.B[2] = pwh + 2 * W; qkv.s[2] = sv; qkv.C[2] = pv;
    gemm512<<<dim3(DIM / 256, (BSZ * SEQ) / 128, 3), 512, G_SMEM>>>(pxh, qkv);

    // 3) RoPE + cache scatter + fp16 emission; tail zero
    rope_cache_kernel<<<BSZ * SEQ, 256>>>(fcos, fsin, idx, cacheK, cacheV);
    zero_tail_kernel<<<2048, 256>>>((float4*)cacheK, (float4*)cacheV);

    // 4) fused flash attention
    flash_kernel<<<dim3(4, BSZ * NHEADS), 256, F_SMEM>>>();

    // 5) output projection
    GemmSet og;
    og.B[0] = pwh + 3 * W; og.s[0] = so; og.C[0] = out;
    og.B[1] = og.B[0]; og.s[1] = og.s[0]; og.C[1] = og.C[0];
    og.B[2] = og.B[0]; og.s[2] = og.s[0]; og.C[2] = og.C[0];
    gemm512<<<dim3(DIM / 256, (BSZ * SEQ) / 128, 1), 512, G_SMEM>>>(pah, og);
}

// round 7
// speedup vs baseline: 1.5350x; 1.0083x over previous
#include <cuda_runtime.h>
#include <cuda_fp16.h>
#include <stdint.h>

#define DIM 4096
#define NHEADS 32
#define HD 128
#define BSZ 4
#define SEQ 512
#define MAXSEQ 2048

// ---------------- scratch ----------------
static __device__ __align__(256) float  g_q[(size_t)BSZ * SEQ * DIM];
static __device__ __align__(256) float  g_k[(size_t)BSZ * SEQ * DIM];
static __device__ __align__(256) float  g_v[(size_t)BSZ * SEQ * DIM];
static __device__ __align__(256) __half g_xh[(size_t)BSZ * SEQ * DIM];
static __device__ __align__(256) __half g_attnh[(size_t)BSZ * SEQ * DIM];
static __device__ __align__(256) __half g_wh[(size_t)4 * DIM * DIM];
static __device__ __align__(256) __half g_qh[(size_t)BSZ * SEQ * DIM];
static __device__ __align__(256) __half g_kh[(size_t)BSZ * SEQ * DIM];
static __device__ __align__(256) __half g_vh[(size_t)BSZ * SEQ * DIM];

// ---------------- helpers ----------------
__device__ __forceinline__ uint32_t smem_u32(const void* p) {
    uint32_t r;
    asm("{ .reg .u64 t; cvta.to.shared.u64 t, %1; cvt.u32.u64 %0, t; }" : "=r"(r) : "l"(p));
    return r;
}

__device__ __forceinline__ void cp16(uint32_t d, const void* g) {
    asm volatile("cp.async.cg.shared.global [%0], [%1], 16;" :: "r"(d), "l"(g) : "memory");
}
#define CP_COMMIT() asm volatile("cp.async.commit_group;" ::: "memory")
#define CP_WAIT1()  asm volatile("cp.async.wait_group 1;" ::: "memory")
#define CP_WAIT0()  asm volatile("cp.async.wait_group 0;" ::: "memory")

__device__ __forceinline__ void ldsm4(uint32_t* r, uint32_t a) {
    asm volatile("ldmatrix.sync.aligned.m8n8.x4.shared.b16 {%0,%1,%2,%3}, [%4];"
                 : "=r"(r[0]), "=r"(r[1]), "=r"(r[2]), "=r"(r[3]) : "r"(a));
}
__device__ __forceinline__ void ldsm4t(uint32_t* r, uint32_t a) {
    asm volatile("ldmatrix.sync.aligned.m8n8.x4.trans.shared.b16 {%0,%1,%2,%3}, [%4];"
                 : "=r"(r[0]), "=r"(r[1]), "=r"(r[2]), "=r"(r[3]) : "r"(a));
}

__device__ __forceinline__ void mma_16816(float* c, const uint32_t* a, const uint32_t* b) {
    asm volatile(
        "mma.sync.aligned.m16n8k16.row.col.f32.f16.f16.f32 "
        "{%0,%1,%2,%3}, {%4,%5,%6,%7}, {%8,%9}, {%0,%1,%2,%3};\n"
        : "+f"(c[0]), "+f"(c[1]), "+f"(c[2]), "+f"(c[3])
        : "r"(a[0]), "r"(a[1]), "r"(a[2]), "r"(a[3]),
          "r"(b[0]), "r"(b[1]));
}

__device__ __forceinline__ uint32_t pack2f(float a, float b) {
    __half2 t = __floats2half2_rn(a, b);
    return *reinterpret_cast<uint32_t*>(&t);
}

constexpr float QK_SCALE = 0.08838834764831845f;  // 1/sqrt(128)

// =====================================================================
//  gemm256: CTA tile 128x256, 256 threads (8 warps), warp tile 64x64,
//  BK=64, 3-stage cp.async, ldmatrix.
//  C[m][n] = scale[n]*sum_k A[m][k]*B[n][k]
// =====================================================================
constexpr int GP = 72;                    // smem pitch (halves)
constexpr int GA_ST = 128 * GP;           // A stage halves
constexpr int GB_ST = 256 * GP;           // B stage halves
constexpr int G_SMEM = 3 * (GA_ST + GB_ST) * 2;

struct GemmSet {
    const __half* B[3];
    const float*  s[3];
    float*        C[3];
};

__global__ void __launch_bounds__(256, 1) gemm256(
    const __half* __restrict__ A, GemmSet gs)
{
    extern __shared__ __half sm[];
    __half* As = sm;                      // [3][128][GP]
    __half* Bs = sm + 3 * GA_ST;          // [3][256][GP]

    const __half* Bw = gs.B[blockIdx.z];
    const float*  scale = gs.s[blockIdx.z];
    float*        C = gs.C[blockIdx.z];

    const int K = DIM;
    const int tid = threadIdx.x;
    const int warp = tid >> 5, lane = tid & 31;
    const int m0 = blockIdx.y * 128, n0 = blockIdx.x * 256;
    const int wm = (warp & 1) * 64, wn = (warp >> 1) * 64;
    const int gid = lane >> 2, t2 = (lane & 3) * 2;

    // ---- loader mapping (rows stride by 32 per j since 256 % 8 == 0) ----
    const int lr = tid >> 3, lsub = (tid & 7) * 8;
    const uint32_t aD0 = smem_u32(As + lr * GP + lsub);
    const uint32_t bD0 = smem_u32(Bs + lr * GP + lsub);
    const __half* Ag = A + (size_t)(m0 + lr) * K + lsub;
    const __half* Bg = Bw + (size_t)(n0 + lr) * K + lsub;

    // ---- fragment lane addressing ----
    const int a_r = (lane & 7) + ((lane >> 3) & 1) * 8;
    const int a_c = ((lane >> 4) & 1) * 8;
    const int b_r = (lane & 7) + ((lane >> 4) & 1) * 8;
    const int b_c = ((lane >> 3) & 1) * 8;
    const uint32_t aF0 = smem_u32(As + (wm + a_r) * GP + a_c);
    const uint32_t bF0 = smem_u32(Bs + (wn + b_r) * GP + b_c);

    float c[4][8][4];
#pragma unroll
    for (int mt = 0; mt < 4; mt++)
#pragma unroll
        for (int nt = 0; nt < 8; nt++)
#pragma unroll
            for (int r = 0; r < 4; r++) c[mt][nt][r] = 0.f;

    // ---- prologue: stages 0,1 ----
#pragma unroll
    for (int s = 0; s < 2; s++) {
        const uint32_t so = (uint32_t)(s * GA_ST * 2);
        const uint32_t sob = (uint32_t)(s * GB_ST * 2);
#pragma unroll
        for (int j = 0; j < 4; j++)
            cp16(aD0 + so + j * 32 * GP * 2, Ag + s * 64 + (size_t)j * 32 * K);
#pragma unroll
        for (int j = 0; j < 8; j++)
            cp16(bD0 + sob + j * 32 * GP * 2, Bg + s * 64 + (size_t)j * 32 * K);
        CP_COMMIT();
    }

    const int NK = K / 64;  // 64
    int s = 0;
    for (int kt = 0; kt < NK; kt++) {
        CP_WAIT1();
        __syncthreads();

        if (kt + 2 < NK) {
            int sn = s + 2; if (sn >= 3) sn -= 3;
            const int ko = (kt + 2) * 64;
            const uint32_t so = (uint32_t)(sn * GA_ST * 2);
            const uint32_t sob = (uint32_t)(sn * GB_ST * 2);
#pragma unroll
            for (int j = 0; j < 4; j++)
                cp16(aD0 + so + j * 32 * GP * 2, Ag + ko + (size_t)j * 32 * K);
#pragma unroll
            for (int j = 0; j < 8; j++)
                cp16(bD0 + sob + j * 32 * GP * 2, Bg + ko + (size_t)j * 32 * K);
        }
        CP_COMMIT();

        const uint32_t aB = aF0 + (uint32_t)(s * GA_ST * 2);
        const uint32_t bB = bF0 + (uint32_t)(s * GB_ST * 2);
#pragma unroll
        for (int kk = 0; kk < 64; kk += 16) {
            uint32_t af[4][4], bf[4][4];
#pragma unroll
            for (int mt = 0; mt < 4; mt++)
                ldsm4(af[mt], aB + (mt * 16 * GP + kk) * 2);
#pragma unroll
            for (int p = 0; p < 4; p++)
                ldsm4(bf[p], bB + (p * 16 * GP + kk) * 2);
#pragma unroll
            for (int mt = 0; mt < 4; mt++)
#pragma unroll
                for (int nt = 0; nt < 8; nt++)
                    mma_16816(c[mt][nt], af[mt], &bf[nt >> 1][(nt & 1) * 2]);
        }
        if (++s == 3) s = 0;
    }

    // ---- epilogue ----
#pragma unroll
    for (int nt = 0; nt < 8; nt++) {
        const int col = n0 + wn + nt * 8 + t2;
        const float s0 = __ldg(scale + col), s1 = __ldg(scale + col + 1);
#pragma unroll
        for (int mt = 0; mt < 4; mt++) {
            const int row = m0 + wm + mt * 16 + gid;
            C[(size_t)row * DIM + col]           = c[mt][nt][0] * s0;
            C[(size_t)row * DIM + col + 1]       = c[mt][nt][1] * s1;
            C[(size_t)(row + 8) * DIM + col]     = c[mt][nt][2] * s0;
            C[(size_t)(row + 8) * DIM + col + 1] = c[mt][nt][3] * s1;
        }
    }
}

// =====================================================================
// conversion kernels (4 weights fused via grid.y)
// =====================================================================
struct WSet { const int4* w[4]; __half* o[4]; };

__global__ void conv_w4_kernel(WSet ws, int n4)
{
    const int4* w = ws.w[blockIdx.y];
    __half* out = ws.o[blockIdx.y];
    for (int i = blockIdx.x * blockDim.x + threadIdx.x; i < n4; i += gridDim.x * blockDim.x) {
        const int4 v = w[i];
        __half2 h0 = __halves2half2(__int2half_rn(v.x), __int2half_rn(v.y));
        __half2 h1 = __halves2half2(__int2half_rn(v.z), __int2half_rn(v.w));
        uint2 u;
        u.x = *reinterpret_cast<uint32_t*>(&h0);
        u.y = *reinterpret_cast<uint32_t*>(&h1);
        ((uint2*)out)[i] = u;
    }
}

__global__ void conv_x_kernel(const float4* __restrict__ x, __half* __restrict__ out, int n4)
{
    for (int i = blockIdx.x * blockDim.x + threadIdx.x; i < n4; i += gridDim.x * blockDim.x) {
        const float4 v = x[i];
        __half2 h0 = __floats2half2_rn(v.x, v.y);
        __half2 h1 = __floats2half2_rn(v.z, v.w);
        uint2 u;
        u.x = *reinterpret_cast<uint32_t*>(&h0);
        u.y = *reinterpret_cast<uint32_t*>(&h1);
        ((uint2*)out)[i] = u;
    }
}

// =====================================================================
// RoPE + cache scatter + fp16 q/k/v emission (q pre-scaled by 1/sqrt(hd))
// =====================================================================
__global__ __launch_bounds__(256) void rope_cache_kernel(
    const float* __restrict__ fcos, const float* __restrict__ fsin,
    const int* __restrict__ idx,
    float* __restrict__ cacheK, float* __restrict__ cacheV)
{
    const int bs = blockIdx.x;
    const int b = bs >> 9, sq = bs & 511;
    const int t = idx[sq];
    const size_t rbase = (size_t)bs * DIM;
    const size_t cbase = ((size_t)(b * MAXSEQ + t)) * DIM;

    for (int u = threadIdx.x; u < 512; u += 256) {
        const int off = u * 8;
        const int p = (u & 15) * 4;
        const float4 c0 = *(const float4*)(fcos + sq * 64 + p);
        const float4 s0 = *(const float4*)(fsin + sq * 64 + p);

        float4 q0 = *(float4*)(g_q + rbase + off);
        float4 q1 = *(float4*)(g_q + rbase + off + 4);
        float4 k0 = *(float4*)(g_k + rbase + off);
        float4 k1 = *(float4*)(g_k + rbase + off + 4);
        float4 v0 = *(float4*)(g_v + rbase + off);
        float4 v1 = *(float4*)(g_v + rbase + off + 4);

        float4 qo0, qo1, ko0, ko1;
        qo0.x = q0.x * c0.x - q0.y * s0.x;  qo0.y = q0.x * s0.x + q0.y * c0.x;
        qo0.z = q0.z * c0.y - q0.w * s0.y;  qo0.w = q0.z * s0.y + q0.w * c0.y;
        qo1.x = q1.x * c0.z - q1.y * s0.z;  qo1.y = q1.x * s0.z + q1.y * c0.z;
        qo1.z = q1.z * c0.w - q1.w * s0.w;  qo1.w = q1.z * s0.w + q1.w * c0.w;
        ko0.x = k0.x * c0.x - k0.y * s0.x;  ko0.y = k0.x * s0.x + k0.y * c0.x;
        ko0.z = k0.z * c0.y - k0.w * s0.y;  ko0.w = k0.z * s0.y + k0.w * c0.y;
        ko1.x = k1.x * c0.z - k1.y * s0.z;  ko1.y = k1.x * s0.z + k1.y * c0.z;
        ko1.z = k1.z * c0.w - k1.w * s0.w;  ko1.w = k1.z * s0.w + k1.w * c0.w;

        *(float4*)(cacheK + cbase + off)     = ko0;
        *(float4*)(cacheK + cbase + off + 4) = ko1;
        *(float4*)(cacheV + cbase + off)     = v0;
        *(float4*)(cacheV + cbase + off + 4) = v1;

        uint2 uq, uk, uv;
        uq.x = pack2f(qo0.x * QK_SCALE, qo0.y * QK_SCALE);
        uq.y = pack2f(qo0.z * QK_SCALE, qo0.w * QK_SCALE);
        *(uint2*)(g_qh + rbase + off) = uq;
        uq.x = pack2f(qo1.x * QK_SCALE, qo1.y * QK_SCALE);
        uq.y = pack2f(qo1.z * QK_SCALE, qo1.w * QK_SCALE);
        *(uint2*)(g_qh + rbase + off + 4) = uq;
        uk.x = pack2f(ko0.x, ko0.y); uk.y = pack2f(ko0.z, ko0.w);
        *(uint2*)(g_kh + rbase + off) = uk;
        uk.x = pack2f(ko1.x, ko1.y); uk.y = pack2f(ko1.z, ko1.w);
        *(uint2*)(g_kh + rbase + off + 4) = uk;
        uv.x = pack2f(v0.x, v0.y); uv.y = pack2f(v0.z, v0.w);
        *(uint2*)(g_vh + rbase + off) = uv;
        uv.x = pack2f(v1.x, v1.y); uv.y = pack2f(v1.z, v1.w);
        *(uint2*)(g_vh + rbase + off + 4) = uv;
    }
}

__global__ void zero_tail_kernel(float4* __restrict__ ck, float4* __restrict__ cv)
{
    const int perB = 1536 * 1024;
    const int n = BSZ * perB;
    const float4 z = make_float4(0.f, 0.f, 0.f, 0.f);
    for (int i = blockIdx.x * blockDim.x + threadIdx.x; i < n; i += gridDim.x * blockDim.x) {
        const int b = i / perB, r = i - b * perB;
        const size_t off = ((size_t)b * MAXSEQ + SEQ) * (DIM / 4) + r;
        ck[off] = z;
        cv[off] = z;
    }
}

// =====================================================================
// Flash attention (proven round-6 version)
// =====================================================================
constexpr int FP = 136;
constexpr int F_TILE = 128 * FP;
constexpr int F_SMEM = 5 * F_TILE * 2;

__global__ __launch_bounds__(256) void flash_kernel()
{
    extern __shared__ __half sm[];
    __half* Qs = sm;
    __half* Ks = sm + F_TILE;
    __half* Vs = sm + 3 * F_TILE;

    const int qt = blockIdx.x;
    const int z  = blockIdx.y;
    const int b = z >> 5, h = z & 31;
    const int tid = threadIdx.x, warp = tid >> 5, lane = tid & 31;
    const int gid = lane >> 2, t2 = (lane & 3) * 2;

    const __half* Qg = g_qh + ((size_t)(b * SEQ + qt * 128)) * DIM + h * HD;
    const __half* Kg = g_kh + ((size_t)b * SEQ) * DIM + h * HD;
    const __half* Vg = g_vh + ((size_t)b * SEQ) * DIM + h * HD;

#pragma unroll
    for (int j = 0; j < 8; j++) {
        const int c = tid + j * 256;
        const int row = c >> 4, sub = (c & 15) * 8;
        cp16(smem_u32(Qs + row * FP + sub), Qg + (size_t)row * DIM + sub);
    }
    CP_COMMIT();
#pragma unroll
    for (int j = 0; j < 8; j++) {
        const int c = tid + j * 256;
        const int row = c >> 4, sub = (c & 15) * 8;
        cp16(smem_u32(Ks + row * FP + sub), Kg + (size_t)row * DIM + sub);
        cp16(smem_u32(Vs + row * FP + sub), Vg + (size_t)row * DIM + sub);
    }
    CP_COMMIT();
    CP_WAIT0();
    __syncthreads();

    const int fr = (lane & 7) + ((lane >> 3) & 1) * 8;
    const int fc = ((lane >> 4) & 1) * 8;
    const int kb_r = (lane & 7) + ((lane >> 4) & 1) * 8;
    const int kb_c = ((lane >> 3) & 1) * 8;

    const uint32_t qB = smem_u32(Qs + (warp * 16 + fr) * FP + fc);

    float o[16][4];
#pragma unroll
    for (int nt = 0; nt < 16; nt++)
#pragma unroll
        for (int r = 0; r < 4; r++) o[nt][r] = 0.f;
    float m0 = -1e30f, m1 = -1e30f, l0 = 0.f, l1 = 0.f;

    for (int kt = 0; kt <= qt; kt++) {
        const int buf = kt & 1;

        if (kt < qt) {
            const __half* Kn = Kg + (size_t)(kt + 1) * 128 * DIM;
            const __half* Vn = Vg + (size_t)(kt + 1) * 128 * DIM;
            __half* Kd = Ks + (buf ^ 1) * F_TILE;
            __half* Vd = Vs + (buf ^ 1) * F_TILE;
#pragma unroll
            for (int j = 0; j < 8; j++) {
                const int c = tid + j * 256;
                const int row = c >> 4, sub = (c & 15) * 8;
                cp16(smem_u32(Kd + row * FP + sub), Kn + (size_t)row * DIM + sub);
                cp16(smem_u32(Vd + row * FP + sub), Vn + (size_t)row * DIM + sub);
            }
            CP_COMMIT();
        }

        const uint32_t kB = smem_u32(Ks + buf * F_TILE + kb_r * FP + kb_c);
        const uint32_t vB = smem_u32(Vs + buf * F_TILE + fr * FP + fc);

        float s[16][4];
#pragma unroll
        for (int nt = 0; nt < 16; nt++)
#pragma unroll
            for (int r = 0; r < 4; r++) s[nt][r] = 0.f;

#pragma unroll
        for (int kk = 0; kk < 8; kk++) {
            uint32_t a[4];
            ldsm4(a, qB + kk * 32);
#pragma unroll
            for (int p = 0; p < 8; p++) {
                uint32_t bk[4];
                ldsm4(bk, kB + (p * 16 * FP + kk * 16) * 2);
                mma_16816(s[2 * p],     a, bk);
                mma_16816(s[2 * p + 1], a, bk + 2);
            }
        }

        if (kt == qt) {
            const int r0 = warp * 16 + gid, r1 = r0 + 8;
#pragma unroll
            for (int nt = 0; nt < 16; nt++) {
                const int c0 = nt * 8 + t2;
                if (c0 > r0)     s[nt][0] = -1e30f;
                if (c0 + 1 > r0) s[nt][1] = -1e30f;
                if (c0 > r1)     s[nt][2] = -1e30f;
                if (c0 + 1 > r1) s[nt][3] = -1e30f;
            }
        }

        float mx0 = -1e30f, mx1 = -1e30f;
#pragma unroll
        for (int nt = 0; nt < 16; nt++) {
            mx0 = fmaxf(mx0, fmaxf(s[nt][0], s[nt][1]));
            mx1 = fmaxf(mx1, fmaxf(s[nt][2], s[nt][3]));
        }
        mx0 = fmaxf(mx0, __shfl_xor_sync(0xffffffffu, mx0, 1));
        mx0 = fmaxf(mx0, __shfl_xor_sync(0xffffffffu, mx0, 2));
        mx1 = fmaxf(mx1, __shfl_xor_sync(0xffffffffu, mx1, 1));
        mx1 = fmaxf(mx1, __shfl_xor_sync(0xffffffffu, mx1, 2));

        const float mn0 = fmaxf(m0, mx0), mn1 = fmaxf(m1, mx1);
        const float sc0 = __expf(m0 - mn0), sc1 = __expf(m1 - mn1);
        m0 = mn0; m1 = mn1;

        float sum0 = 0.f, sum1 = 0.f;
#pragma unroll
        for (int nt = 0; nt < 16; nt++) {
            s[nt][0] = __expf(s[nt][0] - mn0);
            s[nt][1] = __expf(s[nt][1] - mn0);
            s[nt][2] = __expf(s[nt][2] - mn1);
            s[nt][3] = __expf(s[nt][3] - mn1);
            sum0 += s[nt][0] + s[nt][1];
            sum1 += s[nt][2] + s[nt][3];
        }
        sum0 += __shfl_xor_sync(0xffffffffu, sum0, 1);
        sum0 += __shfl_xor_sync(0xffffffffu, sum0, 2);
        sum1 += __shfl_xor_sync(0xffffffffu, sum1, 1);
        sum1 += __shfl_xor_sync(0xffffffffu, sum1, 2);
        l0 = l0 * sc0 + sum0;
        l1 = l1 * sc1 + sum1;

#pragma unroll
        for (int nt = 0; nt < 16; nt++) {
            o[nt][0] *= sc0; o[nt][1] *= sc0;
            o[nt][2] *= sc1; o[nt][3] *= sc1;
        }

#pragma unroll
        for (int ks = 0; ks < 8; ks++) {
            uint32_t pa[4];
            pa[0] = pack2f(s[2 * ks][0],     s[2 * ks][1]);
            pa[1] = pack2f(s[2 * ks][2],     s[2 * ks][3]);
            pa[2] = pack2f(s[2 * ks + 1][0], s[2 * ks + 1][1]);
            pa[3] = pack2f(s[2 * ks + 1][2], s[2 * ks + 1][3]);
#pragma unroll
            for (int dp = 0; dp < 8; dp++) {
                uint32_t vb[4];
                ldsm4t(vb, vB + (ks * 16 * FP + dp * 16) * 2);
                mma_16816(o[2 * dp],     pa, vb);
                mma_16816(o[2 * dp + 1], pa, vb + 2);
            }
        }

        if (kt < qt) {
            CP_WAIT0();
            __syncthreads();
        }
    }

    const float i0 = 1.f / l0, i1 = 1.f / l1;
    const int r0 = qt * 128 + warp * 16 + gid;
    __half* O0 = g_attnh + (size_t)(b * SEQ + r0) * DIM + h * HD;
    __half* O1 = O0 + (size_t)8 * DIM;
#pragma unroll
    for (int nt = 0; nt < 16; nt++) {
        const int col = nt * 8 + t2;
        *(uint32_t*)(O0 + col) = pack2f(o[nt][0] * i0, o[nt][1] * i0);
        *(uint32_t*)(O1 + col) = pack2f(o[nt][2] * i1, o[nt][3] * i1);
    }
}

// =====================================================================
extern "C" void kernel_launch(void* const* d_in, const int* in_sizes, int n_in,
                              void* d_out, int out_size)
{
    (void)in_sizes; (void)n_in; (void)out_size;
    const float* x    = (const float*)d_in[0];
    const float* fcos = (const float*)d_in[1];
    const float* fsin = (const float*)d_in[2];
    const int*   idx  = (const int*)d_in[4];
    const int*   wq   = (const int*)d_in[7];
    const float* sq   = (const float*)d_in[8];
    const int*   wk   = (const int*)d_in[9];
    const float* sk   = (const float*)d_in[10];
    const int*   wv   = (const int*)d_in[11];
    const float* sv   = (const float*)d_in[12];
    const int*   wo   = (const int*)d_in[13];
    const float* so   = (const float*)d_in[14];

    float* out    = (float*)d_out;
    float* cacheK = out + (size_t)BSZ * SEQ * DIM;
    float* cacheV = cacheK + (size_t)BSZ * MAXSEQ * NHEADS * HD;

    float  *pq = nullptr, *pk = nullptr, *pv = nullptr;
    __half *pxh = nullptr, *pwh = nullptr, *pah = nullptr;
    cudaGetSymbolAddress((void**)&pq, g_q);
    cudaGetSymbolAddress((void**)&pk, g_k);
    cudaGetSymbolAddress((void**)&pv, g_v);
    cudaGetSymbolAddress((void**)&pxh, g_xh);
    cudaGetSymbolAddress((void**)&pwh, g_wh);
    cudaGetSymbolAddress((void**)&pah, g_attnh);

    cudaFuncSetAttribute(gemm256, cudaFuncAttributeMaxDynamicSharedMemorySize, G_SMEM);
    cudaFuncSetAttribute(flash_kernel, cudaFuncAttributeMaxDynamicSharedMemorySize, F_SMEM);

    const size_t W = (size_t)DIM * DIM;

    // 1) conversions
    conv_x_kernel<<<1184, 256>>>((const float4*)x, pxh, (int)(BSZ * SEQ * DIM / 4));
    WSet ws;
    ws.w[0] = (const int4*)wq; ws.o[0] = pwh + 0 * W;
    ws.w[1] = (const int4*)wk; ws.o[1] = pwh + 1 * W;
    ws.w[2] = (const int4*)wv; ws.o[2] = pwh + 2 * W;
    ws.w[3] = (const int4*)wo; ws.o[3] = pwh + 3 * W;
    conv_w4_kernel<<<dim3(1184, 4), 256>>>(ws, (int)(W / 4));

    // 2) fused QKV projection
    GemmSet qkv;
    qkv.B[0] = pwh + 0 * W; qkv.s[0] = sq; qkv.C[0] = pq;
    qkv.B[1] = pwh + 1 * W; qkv.s[1] = sk; qkv.C[1] = pk;
    qkv.B[2] = pwh + 2 * W; qkv.s[2] = sv; qkv.C[2] = pv;
    gemm256<<<dim3(DIM / 256, (BSZ * SEQ) / 128, 3), 256, G_SMEM>>>(pxh, qkv);

    // 3) RoPE + cache scatter + fp16 emission; tail zero
    rope_cache_kernel<<<BSZ * SEQ, 256>>>(fcos, fsin, idx, cacheK, cacheV);
    zero_tail_kernel<<<2048, 256>>>((float4*)cacheK, (float4*)cacheV);

    // 4) fused flash attention
    flash_kernel<<<dim3(4, BSZ * NHEADS), 256, F_SMEM>>>();

    // 5) output projection
    GemmSet og;
    og.B[0] = pwh + 3 * W; og.s[0] = so; og.C[0] = out;
    og.B[1] = og.B[0]; og.s[1] = og.s[0]; og.C[1] = og.C[0];
    og.B[2] = og.B[0]; og.s[2] = og.s[0]; og.C[2] = og.C[0];
    gemm256<<<dim3(DIM / 256, (BSZ * SEQ) / 128, 1), 256, G_SMEM>>>(pah, og);
}